// round 12
// baseline (speedup 1.0000x reference)
#include <cuda_runtime.h>
#include <cuda_bf16.h>
#include <math.h>
#include <stdint.h>

// ---------------- problem constants ----------------
#define N_SRC1 1210000
#define N_DST1 110000
#define N_SRC2 110000
#define N_DST2 10000
#define E1 1100000
#define E2 100000
#define IN_DIM 128
#define HID_DIM 256
#define OUT_DIM 128

// scan decomposition
#define SCAN_CHUNK 4096
#define NB1 ((N_DST1 + SCAN_CHUNK - 1) / SCAN_CHUNK)
#define NB2 ((N_DST2 + SCAN_CHUNK - 1) / SCAN_CHUNK)
#define NBT (NB1 + NB2)

// layer-1 pipeline chunking
#define NCHUNK 4

// ---------------- scratch (device globals; no runtime alloc) ----------------
__device__ __nv_bfloat16 g_agg1h[(size_t)N_DST1 * IN_DIM];  // pre-split layer-1 agg
__device__ __nv_bfloat16 g_agg1l[(size_t)N_DST1 * IN_DIM];
__device__ float g_h1[(size_t)N_DST1 * HID_DIM];     // UNGATED layer-1 output
__device__ float g_alpha1[N_DST1];                   // layer-1 gate
__device__ float g_agg2[(size_t)N_DST2 * HID_DIM];
__device__ int   g_outdeg1[N_SRC1];
__device__ int   g_indeg1[N_DST1];
__device__ int   g_outdeg2[N_SRC2];
__device__ int   g_indeg2[N_DST2];
__device__ float g_invout1[N_SRC1];
__device__ float g_invin1[N_DST1];
__device__ float g_invout2[N_SRC2];
__device__ float g_invin2[N_DST2];
__device__ int g_offs1[N_DST1 + 1];
__device__ int g_cursor1[N_DST1];
__device__ int g_csr1[E1];
__device__ int g_offs2[N_DST2 + 1];
__device__ int g_cursor2[N_DST2];
__device__ int g_csr2[E2];
__device__ int g_bsum[NBT];
// split bf16 weights, transposed to [N][K]
__device__ __nv_bfloat16 g_w1h[HID_DIM * IN_DIM];
__device__ __nv_bfloat16 g_w1l[HID_DIM * IN_DIM];
__device__ __nv_bfloat16 g_w2h[OUT_DIM * HID_DIM];
__device__ __nv_bfloat16 g_w2l[OUT_DIM * HID_DIM];

// ---------------- helpers ----------------
__device__ __forceinline__ uint32_t smem_u32(const void* p) {
    uint32_t a;
    asm("{ .reg .u64 t; cvta.to.shared.u64 t, %1; cvt.u32.u64 %0, t; }"
        : "=r"(a) : "l"(p));
    return a;
}
__device__ __forceinline__ uint32_t packbf(__nv_bfloat16 a, __nv_bfloat16 b) {
    return ((uint32_t)__bfloat16_as_ushort(b) << 16) | __bfloat16_as_ushort(a);
}
__device__ __forceinline__ void split2(float a, float b, uint32_t& hi, uint32_t& lo) {
    __nv_bfloat16 ah = __float2bfloat16(a), bh = __float2bfloat16(b);
    __nv_bfloat16 al = __float2bfloat16(a - __bfloat162float(ah));
    __nv_bfloat16 bl = __float2bfloat16(b - __bfloat162float(bh));
    hi = packbf(ah, bh);
    lo = packbf(al, bl);
}
__device__ __forceinline__ void ldm4(uint32_t addr, uint32_t* r) {
    asm volatile("ldmatrix.sync.aligned.m8n8.x4.shared.b16 {%0,%1,%2,%3}, [%4];"
                 : "=r"(r[0]), "=r"(r[1]), "=r"(r[2]), "=r"(r[3]) : "r"(addr));
}
__device__ __forceinline__ void mma16816(float* d, const uint32_t* a,
                                         uint32_t b0, uint32_t b1) {
    asm volatile(
        "mma.sync.aligned.m16n8k16.row.col.f32.bf16.bf16.f32 "
        "{%0,%1,%2,%3}, {%4,%5,%6,%7}, {%8,%9}, {%0,%1,%2,%3};"
        : "+f"(d[0]), "+f"(d[1]), "+f"(d[2]), "+f"(d[3])
        : "r"(a[0]), "r"(a[1]), "r"(a[2]), "r"(a[3]), "r"(b0), "r"(b1));
}
__device__ __forceinline__ void cpa16(uint32_t dst, const void* src) {
    asm volatile("cp.async.cg.shared.global [%0], [%1], 16;" :: "r"(dst), "l"(src));
}
#define CP_COMMIT() asm volatile("cp.async.commit_group;" ::: "memory")
#define CP_WAIT0()  asm volatile("cp.async.wait_group 0;" ::: "memory")

// ---------------- 1. init: zero counters + split/transpose weights ----------------
__global__ void init_all(const float* __restrict__ W1, const float* __restrict__ W2) {
    int i = blockIdx.x * blockDim.x + threadIdx.x;
    if (i == 0) { g_offs1[N_DST1] = E1; g_offs2[N_DST2] = E2; }
    if (i < N_SRC1)  g_outdeg1[i] = 0;
    if (i < N_DST1) { g_indeg1[i] = 0; g_outdeg2[i] = 0; }
    if (i < N_DST2)  g_indeg2[i] = 0;
    if (i < IN_DIM * HID_DIM) {                  // W1 [128 k][256 n]
        int k = i / HID_DIM, n = i % HID_DIM;
        float x = W1[i];
        __nv_bfloat16 h = __float2bfloat16(x);
        __nv_bfloat16 l = __float2bfloat16(x - __bfloat162float(h));
        g_w1h[n * IN_DIM + k] = h;
        g_w1l[n * IN_DIM + k] = l;
    }
    int j = i - IN_DIM * HID_DIM;
    if (j >= 0 && j < HID_DIM * OUT_DIM) {       // W2 [256 k][128 n]
        int k = j / OUT_DIM, n = j % OUT_DIM;
        float x = W2[j];
        __nv_bfloat16 h = __float2bfloat16(x);
        __nv_bfloat16 l = __float2bfloat16(x - __bfloat162float(h));
        g_w2h[n * HID_DIM + k] = h;
        g_w2l[n * HID_DIM + k] = l;
    }
}

// ---------------- 2. degree counting (both layers) ----------------
__global__ void count_all(const int* __restrict__ s1, const int* __restrict__ d1,
                          const int* __restrict__ s2, const int* __restrict__ d2) {
    int i = blockIdx.x * blockDim.x + threadIdx.x;
    if (i < E1) { atomicAdd(&g_outdeg1[s1[i]], 1); atomicAdd(&g_indeg1[d1[i]], 1); }
    if (i < E2) { atomicAdd(&g_outdeg2[s2[i]], 1); atomicAdd(&g_indeg2[d2[i]], 1); }
}

// ---------------- 3. scan phase A: per-chunk reduce ----------------
__global__ void __launch_bounds__(512) scan_reduce() {
    int layer = (blockIdx.x < NB1) ? 0 : 1;
    const int* deg = layer ? g_indeg2 : g_indeg1;
    int n = layer ? N_DST2 : N_DST1;
    int chunk = layer ? (blockIdx.x - NB1) : blockIdx.x;
    int base = chunk * SCAN_CHUNK + threadIdx.x * 8;
    int s = 0;
#pragma unroll
    for (int l = 0; l < 8; l++) { int i = base + l; if (i < n) s += deg[i]; }
#pragma unroll
    for (int o = 16; o > 0; o >>= 1) s += __shfl_xor_sync(0xffffffffu, s, o);
    __shared__ int ws[16];
    int lane = threadIdx.x & 31, wid = threadIdx.x >> 5;
    if (lane == 0) ws[wid] = s;
    __syncthreads();
    if (threadIdx.x < 16) {
        int v = ws[threadIdx.x];
#pragma unroll
        for (int o = 8; o > 0; o >>= 1) v += __shfl_xor_sync(0xffffu, v, o);
        if (threadIdx.x == 0) g_bsum[blockIdx.x] = v;
    }
}

// ---------------- 4. scan phase B: apply (inline spine) ----------------
__global__ void __launch_bounds__(512) scan_apply() {
    int layer = (blockIdx.x < NB1) ? 0 : 1;
    const int* deg = layer ? g_indeg2 : g_indeg1;
    int* offs      = layer ? g_offs2 : g_offs1;
    int* cursor    = layer ? g_cursor2 : g_cursor1;
    int n          = layer ? N_DST2 : N_DST1;
    int lo         = layer ? NB1 : 0;
    int chunk = blockIdx.x - lo;
    int base = chunk * SCAN_CHUNK + threadIdx.x * 8;

    __shared__ int sPre;
    if (threadIdx.x < 32) {
        int v = ((int)threadIdx.x < chunk) ? g_bsum[lo + threadIdx.x] : 0;
#pragma unroll
        for (int o = 16; o > 0; o >>= 1) v += __shfl_xor_sync(0xffffffffu, v, o);
        if (threadIdx.x == 0) sPre = v;
    }

    int v[8], ex[8];
    int tsum = 0;
#pragma unroll
    for (int l = 0; l < 8; l++) {
        int i = base + l;
        v[l] = (i < n) ? deg[i] : 0;
        ex[l] = tsum;
        tsum += v[l];
    }
    int lane = threadIdx.x & 31, wid = threadIdx.x >> 5;
    int incl = tsum;
#pragma unroll
    for (int o = 1; o < 32; o <<= 1) {
        int y = __shfl_up_sync(0xffffffffu, incl, o);
        if (lane >= o) incl += y;
    }
    __shared__ int ws[16];
    if (lane == 31) ws[wid] = incl;
    __syncthreads();
    if (threadIdx.x < 16) {
        int w = ws[threadIdx.x];
#pragma unroll
        for (int o = 1; o < 16; o <<= 1) {
            int y = __shfl_up_sync(0xffffu, w, o);
            if ((int)threadIdx.x >= o) w += y;
        }
        ws[threadIdx.x] = w;
    }
    __syncthreads();
    int thread_excl = sPre + (wid ? ws[wid - 1] : 0) + (incl - tsum);
#pragma unroll
    for (int l = 0; l < 8; l++) {
        int i = base + l;
        if (i < n) { int e = thread_excl + ex[l]; offs[i] = e; cursor[i] = e; }
    }
}

// ---------------- 5. fill CSR + inverse-sqrt degrees (merged) ----------------
__global__ void fill_inv(const int* __restrict__ s1, const int* __restrict__ d1,
                         const int* __restrict__ s2, const int* __restrict__ d2) {
    int i = blockIdx.x * blockDim.x + threadIdx.x;
    if (i < E1) { int pos = atomicAdd(&g_cursor1[d1[i]], 1); g_csr1[pos] = s1[i]; }
    if (i < E2) { int pos = atomicAdd(&g_cursor2[d2[i]], 1); g_csr2[pos] = s2[i]; }
    if (i < N_SRC1) { int d = g_outdeg1[i]; g_invout1[i] = rsqrtf((float)(d < 1 ? 1 : d)); }
    if (i < N_DST1) {
        int d = g_indeg1[i];  g_invin1[i]  = rsqrtf((float)(d < 1 ? 1 : d));
        int e = g_outdeg2[i]; g_invout2[i] = rsqrtf((float)(e < 1 ? 1 : e));
    }
    if (i < N_DST2) { int d = g_indeg2[i]; g_invin2[i] = rsqrtf((float)(d < 1 ? 1 : d)); }
}

// ---------------- 6. layer-1 gather (row-windowed) -> pre-split bf16 hi/lo -------
__global__ void __launch_bounds__(256) gather1(const float* __restrict__ feat,
                                               int row0, int nrows_chunk) {
    int w = (blockIdx.x * blockDim.x + threadIdx.x) >> 5;
    int lane = threadIdx.x & 31;
    if (w >= nrows_chunk) return;
    int row = row0 + w;
    int beg = g_offs1[row], end = g_offs1[row + 1];
    float4 acc = make_float4(0.f, 0.f, 0.f, 0.f);
    for (int base = beg; base < end; base += 32) {
        int cnt = min(end - base, 32);
        int s_l = 0; float sc_l = 0.f;
        if (lane < cnt) { s_l = g_csr1[base + lane]; sc_l = g_invout1[s_l]; }
        for (int j = 0; j < cnt; j++) {
            int s = __shfl_sync(0xffffffffu, s_l, j);
            float sc = __shfl_sync(0xffffffffu, sc_l, j);
            float4 v = *(const float4*)(feat + (size_t)s * IN_DIM + lane * 4);
            acc.x = fmaf(v.x, sc, acc.x);
            acc.y = fmaf(v.y, sc, acc.y);
            acc.z = fmaf(v.z, sc, acc.z);
            acc.w = fmaf(v.w, sc, acc.w);
        }
    }
    float r = g_invin1[row];
    uint32_t h0, l0, h1, l1;
    split2(acc.x * r, acc.y * r, h0, l0);
    split2(acc.z * r, acc.w * r, h1, l1);
    *(uint2*)(g_agg1h + (size_t)row * IN_DIM + lane * 4) = make_uint2(h0, h1);
    *(uint2*)(g_agg1l + (size_t)row * IN_DIM + lane * 4) = make_uint2(l0, l1);
}

// ---------------- 8. layer-2 gather (gate folded: scale = invout2 * alpha1) -----
__global__ void __launch_bounds__(256) gather2() {
    int warp = (blockIdx.x * blockDim.x + threadIdx.x) >> 5;
    int lane = threadIdx.x & 31;
    if (warp >= N_DST2) return;
    int beg = g_offs2[warp], end = g_offs2[warp + 1];
    float4 a0 = make_float4(0.f, 0.f, 0.f, 0.f);
    float4 a1 = make_float4(0.f, 0.f, 0.f, 0.f);
    for (int base = beg; base < end; base += 32) {
        int cnt = min(end - base, 32);
        int s_l = 0; float sc_l = 0.f;
        if (lane < cnt) {
            s_l = g_csr2[base + lane];
            sc_l = g_invout2[s_l] * g_alpha1[s_l];
        }
        for (int j = 0; j < cnt; j++) {
            int s = __shfl_sync(0xffffffffu, s_l, j);
            float sc = __shfl_sync(0xffffffffu, sc_l, j);
            const float* row = g_h1 + (size_t)s * HID_DIM;
            float4 v0 = *(const float4*)(row + lane * 4);
            float4 v1 = *(const float4*)(row + 128 + lane * 4);
            a0.x = fmaf(v0.x, sc, a0.x); a0.y = fmaf(v0.y, sc, a0.y);
            a0.z = fmaf(v0.z, sc, a0.z); a0.w = fmaf(v0.w, sc, a0.w);
            a1.x = fmaf(v1.x, sc, a1.x); a1.y = fmaf(v1.y, sc, a1.y);
            a1.z = fmaf(v1.z, sc, a1.z); a1.w = fmaf(v1.w, sc, a1.w);
        }
    }
    float r = g_invin2[warp];
    float* orow = g_agg2 + (size_t)warp * HID_DIM;
    *(float4*)(orow + lane * 4) = make_float4(a0.x * r, a0.y * r, a0.z * r, a0.w * r);
    *(float4*)(orow + 128 + lane * 4) = make_float4(a1.x * r, a1.y * r, a1.z * r, a1.w * r);
}

// ---------------- 7. PIPELINED layer-1 GEMM (tile-windowed) ----------------
// M=64, K=128, N=256, 256 threads: NWN=4, NWM=2, MF=2. cp.async double-buffered A.
__global__ void __launch_bounds__(256, 1)
mma_gemm1(const __nv_bfloat16* __restrict__ aggh,
          const __nv_bfloat16* __restrict__ aggl,
          const __nv_bfloat16* __restrict__ wh, const __nv_bfloat16* __restrict__ wl,
          const float* __restrict__ bias, const float* __restrict__ attn,
          float* __restrict__ out, float* __restrict__ alpha_out,
          int nrows, int t0, int t1) {
    constexpr int M = 64, K = IN_DIM, N = HID_DIM;
    constexpr int NWN = 4, NWM = 2, MF = 2;
    constexpr int LDA = K + 8;
    constexpr int LDB = K + 8;
    constexpr int KS = K / 16;
    constexpr int AOFF = M * LDA * 2;      // bytes: hi block -> lo block
    constexpr int BUFB = 2 * AOFF;         // bytes per (hi+lo) buffer

    extern __shared__ char smem[];
    __nv_bfloat16* sA = (__nv_bfloat16*)smem;               // [2][2][M][LDA]
    __nv_bfloat16* sBh = sA + 2 * 2 * M * LDA;
    __nv_bfloat16* sBl = sBh + N * LDB;
    float* sBias  = (float*)(sBl + N * LDB);
    float* sAttn  = sBias + N;
    float* sRowP  = sAttn + N;             // [M][NWN]
    float* sAlpha = sRowP + M * NWN;       // [M]

    int tid = threadIdx.x, lane = tid & 31, wid = tid >> 5;
    int mw = wid & (NWM - 1), nw = wid / NWM;
    uint32_t sA32 = smem_u32(sA);
    uint32_t sBh32 = smem_u32(sBh), sBl32 = smem_u32(sBl);

    int tfirst = t0 + blockIdx.x;
    // prefetch first tile (buffer 0), then load W while it flies
    if (tfirst < t1) {
#pragma unroll
        for (int l = 0; l < 4; l++) {
            int i = tid + l * 256;          // 0..1023
            int row = i >> 4, c = i & 15;
            int gr = tfirst * M + row; if (gr >= nrows) gr = nrows - 1;
            cpa16(sA32 + row * (LDA * 2) + c * 16, aggh + (size_t)gr * K + c * 8);
            cpa16(sA32 + AOFF + row * (LDA * 2) + c * 16, aggl + (size_t)gr * K + c * 8);
        }
    }
    CP_COMMIT();
    for (int i = tid; i < N * K / 8; i += 256) {
        int n = i / (K / 8), k8 = (i % (K / 8)) * 8;
        *(uint4*)&sBh[n * LDB + k8] = *(const uint4*)&wh[n * K + k8];
        *(uint4*)&sBl[n * LDB + k8] = *(const uint4*)&wl[n * K + k8];
    }
    for (int c = tid; c < N; c += 256) { sBias[c] = bias[c]; sAttn[c] = attn[c]; }

    int quad = lane >> 3, r = lane & 7;
    int aRow = mw * (MF * 16) + (quad & 1) * 8 + r;
    int bRow = nw * 64 + (quad >> 1) * 8 + r;
    int aColB = (quad >> 1) * 16;
    int bColB = (quad & 1) * 16;

    int buf = 0;
    for (int t = tfirst; t < t1; t += gridDim.x) {
        CP_WAIT0();
        __syncthreads();                    // buf holds tile t, W ready

        int tn = t + gridDim.x;
        if (tn < t1) {
            uint32_t base = sA32 + (buf ^ 1) * BUFB;
#pragma unroll
            for (int l = 0; l < 4; l++) {
                int i = tid + l * 256;
                int row = i >> 4, c = i & 15;
                int gr = tn * M + row; if (gr >= nrows) gr = nrows - 1;
                cpa16(base + row * (LDA * 2) + c * 16, aggh + (size_t)gr * K + c * 8);
                cpa16(base + AOFF + row * (LDA * 2) + c * 16, aggl + (size_t)gr * K + c * 8);
            }
        }
        CP_COMMIT();

        uint32_t sAh32 = sA32 + buf * BUFB;
        uint32_t sAl32 = sAh32 + AOFF;

        // ---- MMA mainloop (product-major) ----
        float c[MF][8][4];
#pragma unroll
        for (int mf = 0; mf < MF; mf++)
#pragma unroll
            for (int nf = 0; nf < 8; nf++)
#pragma unroll
                for (int q = 0; q < 4; q++) c[mf][nf][q] = 0.f;

#pragma unroll
        for (int ks = 0; ks < KS; ks++) {
            uint32_t ah[MF][4], al[MF][4];
#pragma unroll
            for (int mf = 0; mf < MF; mf++) {
                uint32_t off = (uint32_t)((aRow + mf * 16) * LDA) * 2 + ks * 32 + aColB;
                ldm4(sAh32 + off, ah[mf]);
                ldm4(sAl32 + off, al[mf]);
            }
#pragma unroll
            for (int np = 0; np < 4; np++) {
                uint32_t bh[4], bl[4];
                uint32_t off = (uint32_t)((bRow + np * 16) * LDB) * 2 + ks * 32 + bColB;
                ldm4(sBh32 + off, bh);
                ldm4(sBl32 + off, bl);
#pragma unroll
                for (int mf = 0; mf < MF; mf++) {
                    mma16816(c[mf][2 * np],     ah[mf], bh[0], bh[1]);
                    mma16816(c[mf][2 * np + 1], ah[mf], bh[2], bh[3]);
                }
#pragma unroll
                for (int mf = 0; mf < MF; mf++) {
                    mma16816(c[mf][2 * np],     ah[mf], bl[0], bl[1]);
                    mma16816(c[mf][2 * np + 1], ah[mf], bl[2], bl[3]);
                }
#pragma unroll
                for (int mf = 0; mf < MF; mf++) {
                    mma16816(c[mf][2 * np],     al[mf], bh[0], bh[1]);
                    mma16816(c[mf][2 * np + 1], al[mf], bh[2], bh[3]);
                }
            }
        }

        // ---- epilogue ----
        int colq = (lane & 3) * 2;
        int rq = lane >> 2;
        float p[MF][2];
#pragma unroll
        for (int mf = 0; mf < MF; mf++) { p[mf][0] = 0.f; p[mf][1] = 0.f; }
#pragma unroll
        for (int mf = 0; mf < MF; mf++)
#pragma unroll
            for (int nf = 0; nf < 8; nf++) {
                int col = nw * 64 + nf * 8 + colq;
                float b0 = sBias[col], b1 = sBias[col + 1];
                float w0 = sAttn[col], w1 = sAttn[col + 1];
                c[mf][nf][0] += b0; c[mf][nf][1] += b1;
                c[mf][nf][2] += b0; c[mf][nf][3] += b1;
                p[mf][0] = fmaf(c[mf][nf][0], w0, fmaf(c[mf][nf][1], w1, p[mf][0]));
                p[mf][1] = fmaf(c[mf][nf][2], w0, fmaf(c[mf][nf][3], w1, p[mf][1]));
            }
#pragma unroll
        for (int mf = 0; mf < MF; mf++) {
#pragma unroll
            for (int o = 1; o <= 2; o <<= 1) {
                p[mf][0] += __shfl_xor_sync(0xffffffffu, p[mf][0], o);
                p[mf][1] += __shfl_xor_sync(0xffffffffu, p[mf][1], o);
            }
            if ((lane & 3) == 0) {
                int row0 = mw * (MF * 16) + mf * 16 + rq;
                sRowP[row0 * NWN + nw]       = p[mf][0];
                sRowP[(row0 + 8) * NWN + nw] = p[mf][1];
            }
        }
        __syncthreads();
        if (tid < M) {
            float s = 0.f;
#pragma unroll
            for (int j = 0; j < NWN; j++) s += sRowP[tid * NWN + j];
            float a = 1.f / (1.f + __expf(-s));
            int g2 = t * M + tid;
            if (g2 < nrows) alpha_out[g2] = a;
        }

        // ---- store (ungated) ----
#pragma unroll
        for (int mf = 0; mf < MF; mf++)
#pragma unroll
            for (int nf = 0; nf < 8; nf++) {
                int row0 = mw * (MF * 16) + mf * 16 + rq;
                int col = nw * 64 + nf * 8 + colq;
#pragma unroll
                for (int h = 0; h < 2; h++) {
                    int row = row0 + h * 8;
                    int gr = t * M + row;
                    if (gr < nrows)
                        *(float2*)(out + (size_t)gr * N + col) =
                            make_float2(c[mf][nf][2 * h], c[mf][nf][2 * h + 1]);
                }
            }
        buf ^= 1;
    }
}

// ---------------- 9. layer-2 GEMM (verified template, 256 thr) ----------------
template <int THREADS, int M, int K, int N, bool GATED>
__global__ void __launch_bounds__(THREADS, 1)
mma_gemm(const float* __restrict__ agg,
         const __nv_bfloat16* __restrict__ wh, const __nv_bfloat16* __restrict__ wl,
         const float* __restrict__ bias, const float* __restrict__ attn,
         float* __restrict__ out, float* __restrict__ alpha_out,
         int nrows, int ntiles) {
    constexpr int NW  = THREADS / 32;
    constexpr int NWN = N / 64;
    constexpr int NWM = NW / NWN;
    constexpr int MF  = M / (NWM * 16);
    constexpr int LDA = K + 8;
    constexpr int LDB = K + 8;
    constexpr int KS  = K / 16;
    constexpr int TPR = THREADS / M;

    extern __shared__ char smem[];
    __nv_bfloat16* sAh = (__nv_bfloat16*)smem;
    __nv_bfloat16* sAl = sAh + M * LDA;
    __nv_bfloat16* sBh = sAl + M * LDA;
    __nv_bfloat16* sBl = sBh + N * LDB;
    float* sBias  = (float*)(sBl + N * LDB);
    float* sAttn  = sBias + N;
    float* sRowP  = sAttn + N;
    float* sAlpha = sRowP + M * NWN;

    int tid = threadIdx.x, lane = tid & 31, wid = tid >> 5;
    int mw = wid & (NWM - 1), nw = wid / NWM;

    for (int i = tid; i < N * K / 8; i += THREADS) {
        int n = i / (K / 8), k8 = (i % (K / 8)) * 8;
        *(uint4*)&sBh[n * LDB + k8] = *(const uint4*)&wh[n * K + k8];
        *(uint4*)&sBl[n * LDB + k8] = *(const uint4*)&wl[n * K + k8];
    }
    for (int c = tid; c < N; c += THREADS) { sBias[c] = bias[c]; sAttn[c] = attn[c]; }

    uint32_t sAh32 = smem_u32(sAh), sAl32 = smem_u32(sAl);
    uint32_t sBh32 = smem_u32(sBh), sBl32 = smem_u32(sBl);

    int quad = lane >> 3, r = lane & 7;
    int aRow = mw * (MF * 16) + (quad & 1) * 8 + r;
    int bRow = nw * 64 + (quad >> 1) * 8 + r;
    int aColB = (quad >> 1) * 16;
    int bColB = (quad & 1) * 16;

    for (int t = blockIdx.x; t < ntiles; t += gridDim.x) {
        {
            int row = tid / TPR, cg = tid % TPR;
            int gr = t * M + row;
            bool v = gr < nrows;
            const float4* ap = (const float4*)(agg + (size_t)gr * K + cg * (K / TPR));
#pragma unroll
            for (int q = 0; q < K / (4 * TPR); q++) {
                float4 f = v ? ap[q] : make_float4(0.f, 0.f, 0.f, 0.f);
                uint32_t h0, l0, h1, l1;
                split2(f.x, f.y, h0, l0);
                split2(f.z, f.w, h1, l1);
                int col = cg * (K / TPR) + q * 4;
                *(uint32_t*)&sAh[row * LDA + col]     = h0;
                *(uint32_t*)&sAh[row * LDA + col + 2] = h1;
                *(uint32_t*)&sAl[row * LDA + col]     = l0;
                *(uint32_t*)&sAl[row * LDA + col + 2] = l1;
            }
        }
        __syncthreads();

        float c[MF][8][4];
#pragma unroll
        for (int mf = 0; mf < MF; mf++)
#pragma unroll
            for (int nf = 0; nf < 8; nf++)
#pragma unroll
                for (int q = 0; q < 4; q++) c[mf][nf][q] = 0.f;

#pragma unroll
        for (int ks = 0; ks < KS; ks++) {
            uint32_t ah[MF][4], al[MF][4];
#pragma unroll
            for (int mf = 0; mf < MF; mf++) {
                uint32_t off = (uint32_t)((aRow + mf * 16) * LDA) * 2 + ks * 32 + aColB;
                ldm4(sAh32 + off, ah[mf]);
                ldm4(sAl32 + off, al[mf]);
            }
#pragma unroll
            for (int np = 0; np < 4; np++) {
                uint32_t bh[4], bl[4];
                uint32_t off = (uint32_t)((bRow + np * 16) * LDB) * 2 + ks * 32 + bColB;
                ldm4(sBh32 + off, bh);
                ldm4(sBl32 + off, bl);
#pragma unroll
                for (int mf = 0; mf < MF; mf++) {
                    mma16816(c[mf][2 * np],     ah[mf], bh[0], bh[1]);
                    mma16816(c[mf][2 * np + 1], ah[mf], bh[2], bh[3]);
                }
#pragma unroll
                for (int mf = 0; mf < MF; mf++) {
                    mma16816(c[mf][2 * np],     ah[mf], bl[0], bl[1]);
                    mma16816(c[mf][2 * np + 1], ah[mf], bl[2], bl[3]);
                }
#pragma unroll
                for (int mf = 0; mf < MF; mf++) {
                    mma16816(c[mf][2 * np],     al[mf], bh[0], bh[1]);
                    mma16816(c[mf][2 * np + 1], al[mf], bh[2], bh[3]);
                }
            }
        }

        int colq = (lane & 3) * 2;
        int rq = lane >> 2;
        float p[MF][2];
#pragma unroll
        for (int mf = 0; mf < MF; mf++) { p[mf][0] = 0.f; p[mf][1] = 0.f; }
#pragma unroll
        for (int mf = 0; mf < MF; mf++)
#pragma unroll
            for (int nf = 0; nf < 8; nf++) {
                int col = nw * 64 + nf * 8 + colq;
                float b0 = sBias[col], b1 = sBias[col + 1];
                float w0 = sAttn[col], w1 = sAttn[col + 1];
                c[mf][nf][0] += b0; c[mf][nf][1] += b1;
                c[mf][nf][2] += b0; c[mf][nf][3] += b1;
                p[mf][0] = fmaf(c[mf][nf][0], w0, fmaf(c[mf][nf][1], w1, p[mf][0]));
                p[mf][1] = fmaf(c[mf][nf][2], w0, fmaf(c[mf][nf][3], w1, p[mf][1]));
            }
#pragma unroll
        for (int mf = 0; mf < MF; mf++) {
#pragma unroll
            for (int o = 1; o <= 2; o <<= 1) {
                p[mf][0] += __shfl_xor_sync(0xffffffffu, p[mf][0], o);
                p[mf][1] += __shfl_xor_sync(0xffffffffu, p[mf][1], o);
            }
            if ((lane & 3) == 0) {
                int row0 = mw * (MF * 16) + mf * 16 + rq;
                sRowP[row0 * NWN + nw]       = p[mf][0];
                sRowP[(row0 + 8) * NWN + nw] = p[mf][1];
            }
        }
        __syncthreads();
        if (tid < M) {
            float s = 0.f;
#pragma unroll
            for (int j = 0; j < NWN; j++) s += sRowP[tid * NWN + j];
            float a = 1.f / (1.f + __expf(-s));
            sAlpha[tid] = a;
            int g2 = t * M + tid;
            if (g2 < nrows) alpha_out[g2] = a;
        }
        __syncthreads();

#pragma unroll
        for (int mf = 0; mf < MF; mf++)
#pragma unroll
            for (int nf = 0; nf < 8; nf++) {
                int row0 = mw * (MF * 16) + mf * 16 + rq;
                int col = nw * 64 + nf * 8 + colq;
#pragma unroll
                for (int h = 0; h < 2; h++) {
                    int row = row0 + h * 8;
                    int gr = t * M + row;
                    if (gr < nrows) {
                        float a = GATED ? sAlpha[row] : 1.f;
                        *(float2*)(out + (size_t)gr * N + col) =
                            make_float2(c[mf][nf][2 * h] * a, c[mf][nf][2 * h + 1] * a);
                    }
                }
            }
    }
}

// ---------------- host launch ----------------
static inline void* symaddr(const void* sym) {
    void* p = nullptr;
    cudaGetSymbolAddress(&p, sym);
    return p;
}

extern "C" void kernel_launch(void* const* d_in, const int* in_sizes, int n_in,
                              void* d_out, int out_size) {
    const float* feat  = (const float*)d_in[0];
    const float* W1    = (const float*)d_in[1];
    const float* b1    = (const float*)d_in[2];
    const float* attn1 = (const float*)d_in[3];
    const float* W2    = (const float*)d_in[4];
    const float* b2    = (const float*)d_in[5];
    const float* attn2 = (const float*)d_in[6];
    const int* src1 = (const int*)d_in[7];
    const int* dst1 = (const int*)d_in[8];
    const int* src2 = (const int*)d_in[9];
    const int* dst2 = (const int*)d_in[10];

    float* out_h     = (float*)d_out;                             // (10000, 128)
    float* out_alpha = (float*)d_out + (size_t)N_DST2 * OUT_DIM;  // (10000, 1)

    __nv_bfloat16* agg1h = (__nv_bfloat16*)symaddr(g_agg1h);
    __nv_bfloat16* agg1l = (__nv_bfloat16*)symaddr(g_agg1l);
    float* h1     = (float*)symaddr(g_h1);
    float* alpha1 = (float*)symaddr(g_alpha1);
    float* agg2   = (float*)symaddr(g_agg2);
    __nv_bfloat16* w1h = (__nv_bfloat16*)symaddr(g_w1h);
    __nv_bfloat16* w1l = (__nv_bfloat16*)symaddr(g_w1l);
    __nv_bfloat16* w2h = (__nv_bfloat16*)symaddr(g_w2h);
    __nv_bfloat16* w2l = (__nv_bfloat16*)symaddr(g_w2l);

    // one-time stream/event creation (never during graph capture: the
    // correctness run happens first). Handle caching only — the launched
    // work is identical on every call.
    static cudaStream_t s2 = nullptr;
    static cudaEvent_t evG[NCHUNK], evDone;
    if (s2 == nullptr) {
        cudaStreamCreateWithFlags(&s2, cudaStreamNonBlocking);
        for (int i = 0; i < NCHUNK; i++)
            cudaEventCreateWithFlags(&evG[i], cudaEventDisableTiming);
        cudaEventCreateWithFlags(&evDone, cudaEventDisableTiming);
    }

    const int T = 256;

    // dynamic smem sizes
    const int LDA1 = IN_DIM + 8;
    const int SM1 = (2 * 2 * 64 * LDA1 + 2 * HID_DIM * LDA1) * 2
                  + (2 * HID_DIM + 64 * 4 + 64) * 4;               // ~207 KB
    const int LDA2 = HID_DIM + 8;
    const int SM2 = (2 * 64 * LDA2 + 2 * OUT_DIM * LDA2) * 2
                  + (2 * OUT_DIM + 64 * 2 + 64) * 4;               // ~204 KB

    cudaFuncSetAttribute(mma_gemm1,
                         cudaFuncAttributeMaxDynamicSharedMemorySize, SM1);
    cudaFuncSetAttribute(mma_gemm<256, 64, HID_DIM, OUT_DIM, true>,
                         cudaFuncAttributeMaxDynamicSharedMemorySize, SM2);

    const int NT1 = (N_DST1 + 63) / 64;    // 1719
    const int NT2 = (N_DST2 + 63) / 64;    // 157
    const int TC  = (NT1 + NCHUNK - 1) / NCHUNK;  // 430 tiles per chunk

    init_all<<<(N_SRC1 + T - 1) / T, T>>>(W1, W2);
    count_all<<<(E1 + T - 1) / T, T>>>(src1, dst1, src2, dst2);
    scan_reduce<<<NBT, 512>>>();
    scan_apply<<<NBT, 512>>>();
    fill_inv<<<(N_SRC1 + T - 1) / T, T>>>(src1, dst1, src2, dst2);

    // gather chunks on main stream; gemm chunks on s2, fork-join via events
    for (int c = 0; c < NCHUNK; c++) {
        int t0 = c * TC;
        int t1 = (t0 + TC < NT1) ? t0 + TC : NT1;
        if (t0 >= t1) { cudaEventRecord(evG[c], 0); continue; }
        int r0 = t0 * 64;
        int rows = t1 * 64; if (rows > N_DST1) rows = N_DST1;
        rows -= r0;
        gather1<<<((long long)rows * 32 + T - 1) / T, T>>>(feat, r0, rows);
        cudaEventRecord(evG[c], 0);
    }
    for (int c = 0; c < NCHUNK; c++) {
        int t0 = c * TC;
        int t1 = (t0 + TC < NT1) ? t0 + TC : NT1;
        cudaStreamWaitEvent(s2, evG[c], 0);
        if (t0 >= t1) continue;
        mma_gemm1<<<148, 256, SM1, s2>>>(
            agg1h, agg1l, w1h, w1l, b1, attn1, h1, alpha1, N_DST1, t0, t1);
    }
    cudaEventRecord(evDone, s2);
    cudaStreamWaitEvent(0, evDone, 0);

    gather2<<<(N_DST2 * 32 + T - 1) / T, T>>>();
    mma_gemm<256, 64, HID_DIM, OUT_DIM, true><<<148, 256, SM2>>>(
        agg2, w2h, w2l, b2, attn2, out_h, out_alpha, N_DST2, NT2);
}

// round 13
// speedup vs baseline: 1.0740x; 1.0740x over previous
#include <cuda_runtime.h>
#include <cuda_bf16.h>
#include <math.h>
#include <stdint.h>

// ---------------- problem constants ----------------
#define N_SRC1 1210000
#define N_DST1 110000
#define N_SRC2 110000
#define N_DST2 10000
#define E1 1100000
#define E2 100000
#define IN_DIM 128
#define HID_DIM 256
#define OUT_DIM 128

// scan decomposition
#define SCAN_CHUNK 4096
#define NB1 ((N_DST1 + SCAN_CHUNK - 1) / SCAN_CHUNK)   // 27
#define NB2 ((N_DST2 + SCAN_CHUNK - 1) / SCAN_CHUNK)   // 3
#define NBT (NB1 + NB2)                                // 30

// ---------------- scratch (device globals; no runtime alloc) ----------------
__device__ __nv_bfloat16 g_agg1h[(size_t)N_DST1 * IN_DIM];  // pre-split layer-1 agg
__device__ __nv_bfloat16 g_agg1l[(size_t)N_DST1 * IN_DIM];
__device__ float g_h1[(size_t)N_DST1 * HID_DIM];     // UNGATED layer-1 output
__device__ float g_alpha1[N_DST1];                   // layer-1 gate
__device__ float g_agg2[(size_t)N_DST2 * HID_DIM];
__device__ int   g_outdeg1[N_SRC1];
__device__ int   g_indeg1[N_DST1];
__device__ int   g_outdeg2[N_SRC2];
__device__ int   g_indeg2[N_DST2];
__device__ int g_offs1[N_DST1 + 1];
__device__ int g_cursor1[N_DST1];
__device__ int g_csr1[E1];
__device__ int g_offs2[N_DST2 + 1];
__device__ int g_cursor2[N_DST2];
__device__ int g_csr2[E2];
__device__ int g_bsum[NBT];
__device__ int g_bflag[NBT];
// split bf16 weights, transposed to [N][K]
__device__ __nv_bfloat16 g_w1h[HID_DIM * IN_DIM];
__device__ __nv_bfloat16 g_w1l[HID_DIM * IN_DIM];
__device__ __nv_bfloat16 g_w2h[OUT_DIM * HID_DIM];
__device__ __nv_bfloat16 g_w2l[OUT_DIM * HID_DIM];

// ---------------- helpers ----------------
__device__ __forceinline__ uint32_t smem_u32(const void* p) {
    uint32_t a;
    asm("{ .reg .u64 t; cvta.to.shared.u64 t, %1; cvt.u32.u64 %0, t; }"
        : "=r"(a) : "l"(p));
    return a;
}
__device__ __forceinline__ uint32_t packbf(__nv_bfloat16 a, __nv_bfloat16 b) {
    return ((uint32_t)__bfloat16_as_ushort(b) << 16) | __bfloat16_as_ushort(a);
}
__device__ __forceinline__ void split2(float a, float b, uint32_t& hi, uint32_t& lo) {
    __nv_bfloat16 ah = __float2bfloat16(a), bh = __float2bfloat16(b);
    __nv_bfloat16 al = __float2bfloat16(a - __bfloat162float(ah));
    __nv_bfloat16 bl = __float2bfloat16(b - __bfloat162float(bh));
    hi = packbf(ah, bh);
    lo = packbf(al, bl);
}
__device__ __forceinline__ void ldm4(uint32_t addr, uint32_t* r) {
    asm volatile("ldmatrix.sync.aligned.m8n8.x4.shared.b16 {%0,%1,%2,%3}, [%4];"
                 : "=r"(r[0]), "=r"(r[1]), "=r"(r[2]), "=r"(r[3]) : "r"(addr));
}
__device__ __forceinline__ void mma16816(float* d, const uint32_t* a,
                                         uint32_t b0, uint32_t b1) {
    asm volatile(
        "mma.sync.aligned.m16n8k16.row.col.f32.bf16.bf16.f32 "
        "{%0,%1,%2,%3}, {%4,%5,%6,%7}, {%8,%9}, {%0,%1,%2,%3};"
        : "+f"(d[0]), "+f"(d[1]), "+f"(d[2]), "+f"(d[3])
        : "r"(a[0]), "r"(a[1]), "r"(a[2]), "r"(a[3]), "r"(b0), "r"(b1));
}
__device__ __forceinline__ void cpa16(uint32_t dst, const void* src) {
    asm volatile("cp.async.cg.shared.global [%0], [%1], 16;" :: "r"(dst), "l"(src));
}
#define CP_COMMIT() asm volatile("cp.async.commit_group;" ::: "memory")
#define CP_WAIT0()  asm volatile("cp.async.wait_group 0;" ::: "memory")

// ---------------- 1. init: zero counters/flags + split/transpose weights --------
__global__ void init_all(const float* __restrict__ W1, const float* __restrict__ W2) {
    int i = blockIdx.x * blockDim.x + threadIdx.x;
    if (i == 0) { g_offs1[N_DST1] = E1; g_offs2[N_DST2] = E2; }
    if (i < NBT)     g_bflag[i] = 0;
    if (i < N_SRC1)  g_outdeg1[i] = 0;
    if (i < N_DST1) { g_indeg1[i] = 0; g_outdeg2[i] = 0; }
    if (i < N_DST2)  g_indeg2[i] = 0;
    if (i < IN_DIM * HID_DIM) {                  // W1 [128 k][256 n]
        int k = i / HID_DIM, n = i % HID_DIM;
        float x = W1[i];
        __nv_bfloat16 h = __float2bfloat16(x);
        __nv_bfloat16 l = __float2bfloat16(x - __bfloat162float(h));
        g_w1h[n * IN_DIM + k] = h;
        g_w1l[n * IN_DIM + k] = l;
    }
    int j = i - IN_DIM * HID_DIM;
    if (j >= 0 && j < HID_DIM * OUT_DIM) {       // W2 [256 k][128 n]
        int k = j / OUT_DIM, n = j % OUT_DIM;
        float x = W2[j];
        __nv_bfloat16 h = __float2bfloat16(x);
        __nv_bfloat16 l = __float2bfloat16(x - __bfloat162float(h));
        g_w2h[n * HID_DIM + k] = h;
        g_w2l[n * HID_DIM + k] = l;
    }
}

// ---------------- 2. degree counting (both layers) ----------------
__global__ void count_all(const int* __restrict__ s1, const int* __restrict__ d1,
                          const int* __restrict__ s2, const int* __restrict__ d2) {
    int i = blockIdx.x * blockDim.x + threadIdx.x;
    if (i < E1) { atomicAdd(&g_outdeg1[s1[i]], 1); atomicAdd(&g_indeg1[d1[i]], 1); }
    if (i < E2) { atomicAdd(&g_outdeg2[s2[i]], 1); atomicAdd(&g_indeg2[d2[i]], 1); }
}

// ---------------- 3. single-kernel scan: decoupled lookback ----------------
// 30 blocks (all wave-1 resident). Block computes its chunk total, publishes
// with fence+flag, lane-parallel lookback over <=27 predecessors, applies.
__global__ void __launch_bounds__(512) scan_lb() {
    int bid = blockIdx.x;
    int tid = threadIdx.x;
    int layer = (bid < NB1) ? 0 : 1;
    const int* deg = layer ? g_indeg2 : g_indeg1;
    int* offs      = layer ? g_offs2 : g_offs1;
    int* cursor    = layer ? g_cursor2 : g_cursor1;
    int n          = layer ? N_DST2 : N_DST1;
    int lo         = layer ? NB1 : 0;
    int chunk = bid - lo;
    int base = chunk * SCAN_CHUNK + tid * 8;

    int v[8], ex[8];
    int tsum = 0;
#pragma unroll
    for (int l = 0; l < 8; l++) {
        int i = base + l;
        v[l] = (i < n) ? deg[i] : 0;
        ex[l] = tsum;
        tsum += v[l];
    }
    int lane = tid & 31, wid = tid >> 5;
    int incl = tsum;
#pragma unroll
    for (int o = 1; o < 32; o <<= 1) {
        int y = __shfl_up_sync(0xffffffffu, incl, o);
        if (lane >= o) incl += y;
    }
    __shared__ int ws[16];
    if (lane == 31) ws[wid] = incl;
    __syncthreads();
    if (tid < 16) {
        int w = ws[tid];
#pragma unroll
        for (int o = 1; o < 16; o <<= 1) {
            int y = __shfl_up_sync(0xffffu, w, o);
            if (tid >= o) w += y;
        }
        ws[tid] = w;
    }
    __syncthreads();
    int total = ws[15];

    __shared__ int sPre;
    if (tid == 0) {
        g_bsum[bid] = total;
        __threadfence();
        atomicExch(&g_bflag[bid], 1);
    }
    if (tid < 32) {
        int idx = lo + tid;
        int vv = 0;
        if (idx < bid) {
            while (atomicAdd((unsigned int*)&g_bflag[idx], 0u) == 0u)
                __nanosleep(100);
            __threadfence();
            vv = g_bsum[idx];
        }
#pragma unroll
        for (int o = 16; o > 0; o >>= 1)
            vv += __shfl_xor_sync(0xffffffffu, vv, o);
        if (tid == 0) sPre = vv;
    }
    __syncthreads();
    int thread_excl = sPre + (wid ? ws[wid - 1] : 0) + (incl - tsum);
#pragma unroll
    for (int l = 0; l < 8; l++) {
        int i = base + l;
        if (i < n) { int e = thread_excl + ex[l]; offs[i] = e; cursor[i] = e; }
    }
}

// ---------------- 4. fill CSR (both layers; inv folded into gathers) -----------
__global__ void fill_csr(const int* __restrict__ s1, const int* __restrict__ d1,
                         const int* __restrict__ s2, const int* __restrict__ d2) {
    int i = blockIdx.x * blockDim.x + threadIdx.x;
    if (i < E1) { int pos = atomicAdd(&g_cursor1[d1[i]], 1); g_csr1[pos] = s1[i]; }
    if (i < E2) { int pos = atomicAdd(&g_cursor2[d2[i]], 1); g_csr2[pos] = s2[i]; }
}

// ---------------- 5. layer-1 gather -> pre-split bf16 hi/lo ----------------
// rsqrt of degrees computed inline (same rsqrtf op -> bit-identical).
__global__ void __launch_bounds__(256) gather1(const float* __restrict__ feat) {
    int warp = (blockIdx.x * blockDim.x + threadIdx.x) >> 5;
    int lane = threadIdx.x & 31;
    if (warp >= N_DST1) return;
    int beg = g_offs1[warp], end = g_offs1[warp + 1];
    float4 acc = make_float4(0.f, 0.f, 0.f, 0.f);
    for (int base = beg; base < end; base += 32) {
        int cnt = min(end - base, 32);
        int s_l = 0; float sc_l = 0.f;
        if (lane < cnt) {
            s_l = g_csr1[base + lane];
            int d = g_outdeg1[s_l];
            sc_l = rsqrtf((float)(d < 1 ? 1 : d));
        }
        for (int j = 0; j < cnt; j++) {
            int s = __shfl_sync(0xffffffffu, s_l, j);
            float sc = __shfl_sync(0xffffffffu, sc_l, j);
            float4 v = *(const float4*)(feat + (size_t)s * IN_DIM + lane * 4);
            acc.x = fmaf(v.x, sc, acc.x);
            acc.y = fmaf(v.y, sc, acc.y);
            acc.z = fmaf(v.z, sc, acc.z);
            acc.w = fmaf(v.w, sc, acc.w);
        }
    }
    int dr = g_indeg1[warp];
    float r = rsqrtf((float)(dr < 1 ? 1 : dr));
    uint32_t h0, l0, h1, l1;
    split2(acc.x * r, acc.y * r, h0, l0);
    split2(acc.z * r, acc.w * r, h1, l1);
    *(uint2*)(g_agg1h + (size_t)warp * IN_DIM + lane * 4) = make_uint2(h0, h1);
    *(uint2*)(g_agg1l + (size_t)warp * IN_DIM + lane * 4) = make_uint2(l0, l1);
}

// ---------------- 7. layer-2 gather (gate folded; inline rsqrt) ----------------
__global__ void __launch_bounds__(256) gather2() {
    int warp = (blockIdx.x * blockDim.x + threadIdx.x) >> 5;
    int lane = threadIdx.x & 31;
    if (warp >= N_DST2) return;
    int beg = g_offs2[warp], end = g_offs2[warp + 1];
    float4 a0 = make_float4(0.f, 0.f, 0.f, 0.f);
    float4 a1 = make_float4(0.f, 0.f, 0.f, 0.f);
    for (int base = beg; base < end; base += 32) {
        int cnt = min(end - base, 32);
        int s_l = 0; float sc_l = 0.f;
        if (lane < cnt) {
            s_l = g_csr2[base + lane];
            int d = g_outdeg2[s_l];
            sc_l = rsqrtf((float)(d < 1 ? 1 : d)) * g_alpha1[s_l];
        }
        for (int j = 0; j < cnt; j++) {
            int s = __shfl_sync(0xffffffffu, s_l, j);
            float sc = __shfl_sync(0xffffffffu, sc_l, j);
            const float* row = g_h1 + (size_t)s * HID_DIM;
            float4 v0 = *(const float4*)(row + lane * 4);
            float4 v1 = *(const float4*)(row + 128 + lane * 4);
            a0.x = fmaf(v0.x, sc, a0.x); a0.y = fmaf(v0.y, sc, a0.y);
            a0.z = fmaf(v0.z, sc, a0.z); a0.w = fmaf(v0.w, sc, a0.w);
            a1.x = fmaf(v1.x, sc, a1.x); a1.y = fmaf(v1.y, sc, a1.y);
            a1.z = fmaf(v1.z, sc, a1.z); a1.w = fmaf(v1.w, sc, a1.w);
        }
    }
    int dr = g_indeg2[warp];
    float r = rsqrtf((float)(dr < 1 ? 1 : dr));
    float* orow = g_agg2 + (size_t)warp * HID_DIM;
    *(float4*)(orow + lane * 4) = make_float4(a0.x * r, a0.y * r, a0.z * r, a0.w * r);
    *(float4*)(orow + 128 + lane * 4) = make_float4(a1.x * r, a1.y * r, a1.z * r, a1.w * r);
}

// ---------------- 6. PIPELINED layer-1 GEMM (verified round-11 code) -----------
// M=64, K=128, N=256, 256 threads: NWN=4, NWM=2, MF=2. cp.async double-buffered A.
__global__ void __launch_bounds__(256, 1)
mma_gemm1(const __nv_bfloat16* __restrict__ aggh,
          const __nv_bfloat16* __restrict__ aggl,
          const __nv_bfloat16* __restrict__ wh, const __nv_bfloat16* __restrict__ wl,
          const float* __restrict__ bias, const float* __restrict__ attn,
          float* __restrict__ out, float* __restrict__ alpha_out,
          int nrows, int ntiles) {
    constexpr int M = 64, K = IN_DIM, N = HID_DIM;
    constexpr int NWN = 4, NWM = 2, MF = 2;
    constexpr int LDA = K + 8;
    constexpr int LDB = K + 8;
    constexpr int KS = K / 16;
    constexpr int AOFF = M * LDA * 2;      // bytes: hi block -> lo block
    constexpr int BUFB = 2 * AOFF;         // bytes per (hi+lo) buffer

    extern __shared__ char smem[];
    __nv_bfloat16* sA = (__nv_bfloat16*)smem;               // [2][2][M][LDA]
    __nv_bfloat16* sBh = sA + 2 * 2 * M * LDA;
    __nv_bfloat16* sBl = sBh + N * LDB;
    float* sBias  = (float*)(sBl + N * LDB);
    float* sAttn  = sBias + N;
    float* sRowP  = sAttn + N;             // [M][NWN]
    float* sAlpha = sRowP + M * NWN;       // [M]

    int tid = threadIdx.x, lane = tid & 31, wid = tid >> 5;
    int mw = wid & (NWM - 1), nw = wid / NWM;
    uint32_t sA32 = smem_u32(sA);
    uint32_t sBh32 = smem_u32(sBh), sBl32 = smem_u32(sBl);

    // prefetch tile 0 (buffer 0) via cp.async, then load W while it flies
    {
        int t0 = blockIdx.x;
#pragma unroll
        for (int l = 0; l < 4; l++) {
            int i = tid + l * 256;          // 0..1023
            int row = i >> 4, c = i & 15;
            int gr = t0 * M + row; if (gr >= nrows) gr = nrows - 1;
            cpa16(sA32 + row * (LDA * 2) + c * 16, aggh + (size_t)gr * K + c * 8);
            cpa16(sA32 + AOFF + row * (LDA * 2) + c * 16, aggl + (size_t)gr * K + c * 8);
        }
        CP_COMMIT();
    }
    for (int i = tid; i < N * K / 8; i += 256) {
        int n = i / (K / 8), k8 = (i % (K / 8)) * 8;
        *(uint4*)&sBh[n * LDB + k8] = *(const uint4*)&wh[n * K + k8];
        *(uint4*)&sBl[n * LDB + k8] = *(const uint4*)&wl[n * K + k8];
    }
    for (int c = tid; c < N; c += 256) { sBias[c] = bias[c]; sAttn[c] = attn[c]; }

    int quad = lane >> 3, r = lane & 7;
    int aRow = mw * (MF * 16) + (quad & 1) * 8 + r;
    int bRow = nw * 64 + (quad >> 1) * 8 + r;
    int aColB = (quad >> 1) * 16;
    int bColB = (quad & 1) * 16;

    int buf = 0;
    for (int t = blockIdx.x; t < ntiles; t += gridDim.x) {
        CP_WAIT0();
        __syncthreads();                    // buf holds tile t, W ready

        int tn = t + gridDim.x;
        if (tn < ntiles) {
            uint32_t base = sA32 + (buf ^ 1) * BUFB;
#pragma unroll
            for (int l = 0; l < 4; l++) {
                int i = tid + l * 256;
                int row = i >> 4, c = i & 15;
                int gr = tn * M + row; if (gr >= nrows) gr = nrows - 1;
                cpa16(base + row * (LDA * 2) + c * 16, aggh + (size_t)gr * K + c * 8);
                cpa16(base + AOFF + row * (LDA * 2) + c * 16, aggl + (size_t)gr * K + c * 8);
            }
        }
        CP_COMMIT();

        uint32_t sAh32 = sA32 + buf * BUFB;
        uint32_t sAl32 = sAh32 + AOFF;

        // ---- MMA mainloop (product-major) ----
        float c[MF][8][4];
#pragma unroll
        for (int mf = 0; mf < MF; mf++)
#pragma unroll
            for (int nf = 0; nf < 8; nf++)
#pragma unroll
                for (int q = 0; q < 4; q++) c[mf][nf][q] = 0.f;

#pragma unroll
        for (int ks = 0; ks < KS; ks++) {
            uint32_t ah[MF][4], al[MF][4];
#pragma unroll
            for (int mf = 0; mf < MF; mf++) {
                uint32_t off = (uint32_t)((aRow + mf * 16) * LDA) * 2 + ks * 32 + aColB;
                ldm4(sAh32 + off, ah[mf]);
                ldm4(sAl32 + off, al[mf]);
            }
#pragma unroll
            for (int np = 0; np < 4; np++) {
                uint32_t bh[4], bl[4];
                uint32_t off = (uint32_t)((bRow + np * 16) * LDB) * 2 + ks * 32 + bColB;
                ldm4(sBh32 + off, bh);
                ldm4(sBl32 + off, bl);
#pragma unroll
                for (int mf = 0; mf < MF; mf++) {
                    mma16816(c[mf][2 * np],     ah[mf], bh[0], bh[1]);
                    mma16816(c[mf][2 * np + 1], ah[mf], bh[2], bh[3]);
                }
#pragma unroll
                for (int mf = 0; mf < MF; mf++) {
                    mma16816(c[mf][2 * np],     ah[mf], bl[0], bl[1]);
                    mma16816(c[mf][2 * np + 1], ah[mf], bl[2], bl[3]);
                }
#pragma unroll
                for (int mf = 0; mf < MF; mf++) {
                    mma16816(c[mf][2 * np],     al[mf], bh[0], bh[1]);
                    mma16816(c[mf][2 * np + 1], al[mf], bh[2], bh[3]);
                }
            }
        }

        // ---- epilogue ----
        int colq = (lane & 3) * 2;
        int rq = lane >> 2;
        float p[MF][2];
#pragma unroll
        for (int mf = 0; mf < MF; mf++) { p[mf][0] = 0.f; p[mf][1] = 0.f; }
#pragma unroll
        for (int mf = 0; mf < MF; mf++)
#pragma unroll
            for (int nf = 0; nf < 8; nf++) {
                int col = nw * 64 + nf * 8 + colq;
                float b0 = sBias[col], b1 = sBias[col + 1];
                float w0 = sAttn[col], w1 = sAttn[col + 1];
                c[mf][nf][0] += b0; c[mf][nf][1] += b1;
                c[mf][nf][2] += b0; c[mf][nf][3] += b1;
                p[mf][0] = fmaf(c[mf][nf][0], w0, fmaf(c[mf][nf][1], w1, p[mf][0]));
                p[mf][1] = fmaf(c[mf][nf][2], w0, fmaf(c[mf][nf][3], w1, p[mf][1]));
            }
#pragma unroll
        for (int mf = 0; mf < MF; mf++) {
#pragma unroll
            for (int o = 1; o <= 2; o <<= 1) {
                p[mf][0] += __shfl_xor_sync(0xffffffffu, p[mf][0], o);
                p[mf][1] += __shfl_xor_sync(0xffffffffu, p[mf][1], o);
            }
            if ((lane & 3) == 0) {
                int row0 = mw * (MF * 16) + mf * 16 + rq;
                sRowP[row0 * NWN + nw]       = p[mf][0];
                sRowP[(row0 + 8) * NWN + nw] = p[mf][1];
            }
        }
        __syncthreads();
        if (tid < M) {
            float s = 0.f;
#pragma unroll
            for (int j = 0; j < NWN; j++) s += sRowP[tid * NWN + j];
            float a = 1.f / (1.f + __expf(-s));
            int g2 = t * M + tid;
            if (g2 < nrows) alpha_out[g2] = a;
        }

        // ---- store (ungated) ----
#pragma unroll
        for (int mf = 0; mf < MF; mf++)
#pragma unroll
            for (int nf = 0; nf < 8; nf++) {
                int row0 = mw * (MF * 16) + mf * 16 + rq;
                int col = nw * 64 + nf * 8 + colq;
#pragma unroll
                for (int h = 0; h < 2; h++) {
                    int row = row0 + h * 8;
                    int gr = t * M + row;
                    if (gr < nrows)
                        *(float2*)(out + (size_t)gr * N + col) =
                            make_float2(c[mf][nf][2 * h], c[mf][nf][2 * h + 1]);
                }
            }
        buf ^= 1;
    }
}

// ---------------- 8. layer-2 GEMM (verified template, 256 thr) ----------------
template <int THREADS, int M, int K, int N, bool GATED>
__global__ void __launch_bounds__(THREADS, 1)
mma_gemm(const float* __restrict__ agg,
         const __nv_bfloat16* __restrict__ wh, const __nv_bfloat16* __restrict__ wl,
         const float* __restrict__ bias, const float* __restrict__ attn,
         float* __restrict__ out, float* __restrict__ alpha_out,
         int nrows, int ntiles) {
    constexpr int NW  = THREADS / 32;
    constexpr int NWN = N / 64;
    constexpr int NWM = NW / NWN;
    constexpr int MF  = M / (NWM * 16);
    constexpr int LDA = K + 8;
    constexpr int LDB = K + 8;
    constexpr int KS  = K / 16;
    constexpr int TPR = THREADS / M;

    extern __shared__ char smem[];
    __nv_bfloat16* sAh = (__nv_bfloat16*)smem;
    __nv_bfloat16* sAl = sAh + M * LDA;
    __nv_bfloat16* sBh = sAl + M * LDA;
    __nv_bfloat16* sBl = sBh + N * LDB;
    float* sBias  = (float*)(sBl + N * LDB);
    float* sAttn  = sBias + N;
    float* sRowP  = sAttn + N;
    float* sAlpha = sRowP + M * NWN;

    int tid = threadIdx.x, lane = tid & 31, wid = tid >> 5;
    int mw = wid & (NWM - 1), nw = wid / NWM;

    for (int i = tid; i < N * K / 8; i += THREADS) {
        int n = i / (K / 8), k8 = (i % (K / 8)) * 8;
        *(uint4*)&sBh[n * LDB + k8] = *(const uint4*)&wh[n * K + k8];
        *(uint4*)&sBl[n * LDB + k8] = *(const uint4*)&wl[n * K + k8];
    }
    for (int c = tid; c < N; c += THREADS) { sBias[c] = bias[c]; sAttn[c] = attn[c]; }

    uint32_t sAh32 = smem_u32(sAh), sAl32 = smem_u32(sAl);
    uint32_t sBh32 = smem_u32(sBh), sBl32 = smem_u32(sBl);

    int quad = lane >> 3, r = lane & 7;
    int aRow = mw * (MF * 16) + (quad & 1) * 8 + r;
    int bRow = nw * 64 + (quad >> 1) * 8 + r;
    int aColB = (quad >> 1) * 16;
    int bColB = (quad & 1) * 16;

    for (int t = blockIdx.x; t < ntiles; t += gridDim.x) {
        {
            int row = tid / TPR, cg = tid % TPR;
            int gr = t * M + row;
            bool v = gr < nrows;
            const float4* ap = (const float4*)(agg + (size_t)gr * K + cg * (K / TPR));
#pragma unroll
            for (int q = 0; q < K / (4 * TPR); q++) {
                float4 f = v ? ap[q] : make_float4(0.f, 0.f, 0.f, 0.f);
                uint32_t h0, l0, h1, l1;
                split2(f.x, f.y, h0, l0);
                split2(f.z, f.w, h1, l1);
                int col = cg * (K / TPR) + q * 4;
                *(uint32_t*)&sAh[row * LDA + col]     = h0;
                *(uint32_t*)&sAh[row * LDA + col + 2] = h1;
                *(uint32_t*)&sAl[row * LDA + col]     = l0;
                *(uint32_t*)&sAl[row * LDA + col + 2] = l1;
            }
        }
        __syncthreads();

        float c[MF][8][4];
#pragma unroll
        for (int mf = 0; mf < MF; mf++)
#pragma unroll
            for (int nf = 0; nf < 8; nf++)
#pragma unroll
                for (int q = 0; q < 4; q++) c[mf][nf][q] = 0.f;

#pragma unroll
        for (int ks = 0; ks < KS; ks++) {
            uint32_t ah[MF][4], al[MF][4];
#pragma unroll
            for (int mf = 0; mf < MF; mf++) {
                uint32_t off = (uint32_t)((aRow + mf * 16) * LDA) * 2 + ks * 32 + aColB;
                ldm4(sAh32 + off, ah[mf]);
                ldm4(sAl32 + off, al[mf]);
            }
#pragma unroll
            for (int np = 0; np < 4; np++) {
                uint32_t bh[4], bl[4];
                uint32_t off = (uint32_t)((bRow + np * 16) * LDB) * 2 + ks * 32 + bColB;
                ldm4(sBh32 + off, bh);
                ldm4(sBl32 + off, bl);
#pragma unroll
                for (int mf = 0; mf < MF; mf++) {
                    mma16816(c[mf][2 * np],     ah[mf], bh[0], bh[1]);
                    mma16816(c[mf][2 * np + 1], ah[mf], bh[2], bh[3]);
                }
#pragma unroll
                for (int mf = 0; mf < MF; mf++) {
                    mma16816(c[mf][2 * np],     ah[mf], bl[0], bl[1]);
                    mma16816(c[mf][2 * np + 1], ah[mf], bl[2], bl[3]);
                }
#pragma unroll
                for (int mf = 0; mf < MF; mf++) {
                    mma16816(c[mf][2 * np],     al[mf], bh[0], bh[1]);
                    mma16816(c[mf][2 * np + 1], al[mf], bh[2], bh[3]);
                }
            }
        }

        int colq = (lane & 3) * 2;
        int rq = lane >> 2;
        float p[MF][2];
#pragma unroll
        for (int mf = 0; mf < MF; mf++) { p[mf][0] = 0.f; p[mf][1] = 0.f; }
#pragma unroll
        for (int mf = 0; mf < MF; mf++)
#pragma unroll
            for (int nf = 0; nf < 8; nf++) {
                int col = nw * 64 + nf * 8 + colq;
                float b0 = sBias[col], b1 = sBias[col + 1];
                float w0 = sAttn[col], w1 = sAttn[col + 1];
                c[mf][nf][0] += b0; c[mf][nf][1] += b1;
                c[mf][nf][2] += b0; c[mf][nf][3] += b1;
                p[mf][0] = fmaf(c[mf][nf][0], w0, fmaf(c[mf][nf][1], w1, p[mf][0]));
                p[mf][1] = fmaf(c[mf][nf][2], w0, fmaf(c[mf][nf][3], w1, p[mf][1]));
            }
#pragma unroll
        for (int mf = 0; mf < MF; mf++) {
#pragma unroll
            for (int o = 1; o <= 2; o <<= 1) {
                p[mf][0] += __shfl_xor_sync(0xffffffffu, p[mf][0], o);
                p[mf][1] += __shfl_xor_sync(0xffffffffu, p[mf][1], o);
            }
            if ((lane & 3) == 0) {
                int row0 = mw * (MF * 16) + mf * 16 + rq;
                sRowP[row0 * NWN + nw]       = p[mf][0];
                sRowP[(row0 + 8) * NWN + nw] = p[mf][1];
            }
        }
        __syncthreads();
        if (tid < M) {
            float s = 0.f;
#pragma unroll
            for (int j = 0; j < NWN; j++) s += sRowP[tid * NWN + j];
            float a = 1.f / (1.f + __expf(-s));
            sAlpha[tid] = a;
            int g2 = t * M + tid;
            if (g2 < nrows) alpha_out[g2] = a;
        }
        __syncthreads();

#pragma unroll
        for (int mf = 0; mf < MF; mf++)
#pragma unroll
            for (int nf = 0; nf < 8; nf++) {
                int row0 = mw * (MF * 16) + mf * 16 + rq;
                int col = nw * 64 + nf * 8 + colq;
#pragma unroll
                for (int h = 0; h < 2; h++) {
                    int row = row0 + h * 8;
                    int gr = t * M + row;
                    if (gr < nrows) {
                        float a = GATED ? sAlpha[row] : 1.f;
                        *(float2*)(out + (size_t)gr * N + col) =
                            make_float2(c[mf][nf][2 * h] * a, c[mf][nf][2 * h + 1] * a);
                    }
                }
            }
    }
}

// ---------------- host launch ----------------
static inline void* symaddr(const void* sym) {
    void* p = nullptr;
    cudaGetSymbolAddress(&p, sym);
    return p;
}

extern "C" void kernel_launch(void* const* d_in, const int* in_sizes, int n_in,
                              void* d_out, int out_size) {
    const float* feat  = (const float*)d_in[0];
    const float* W1    = (const float*)d_in[1];
    const float* b1    = (const float*)d_in[2];
    const float* attn1 = (const float*)d_in[3];
    const float* W2    = (const float*)d_in[4];
    const float* b2    = (const float*)d_in[5];
    const float* attn2 = (const float*)d_in[6];
    const int* src1 = (const int*)d_in[7];
    const int* dst1 = (const int*)d_in[8];
    const int* src2 = (const int*)d_in[9];
    const int* dst2 = (const int*)d_in[10];

    float* out_h     = (float*)d_out;                             // (10000, 128)
    float* out_alpha = (float*)d_out + (size_t)N_DST2 * OUT_DIM;  // (10000, 1)

    __nv_bfloat16* agg1h = (__nv_bfloat16*)symaddr(g_agg1h);
    __nv_bfloat16* agg1l = (__nv_bfloat16*)symaddr(g_agg1l);
    float* h1     = (float*)symaddr(g_h1);
    float* alpha1 = (float*)symaddr(g_alpha1);
    float* agg2   = (float*)symaddr(g_agg2);
    __nv_bfloat16* w1h = (__nv_bfloat16*)symaddr(g_w1h);
    __nv_bfloat16* w1l = (__nv_bfloat16*)symaddr(g_w1l);
    __nv_bfloat16* w2h = (__nv_bfloat16*)symaddr(g_w2h);
    __nv_bfloat16* w2l = (__nv_bfloat16*)symaddr(g_w2l);

    const int T = 256;

    // dynamic smem sizes
    const int LDA1 = IN_DIM + 8;
    const int SM1 = (2 * 2 * 64 * LDA1 + 2 * HID_DIM * LDA1) * 2
                  + (2 * HID_DIM + 64 * 4 + 64) * 4;               // ~207 KB
    const int LDA2 = HID_DIM + 8;
    const int SM2 = (2 * 64 * LDA2 + 2 * OUT_DIM * LDA2) * 2
                  + (2 * OUT_DIM + 64 * 2 + 64) * 4;               // ~204 KB

    cudaFuncSetAttribute(mma_gemm1,
                         cudaFuncAttributeMaxDynamicSharedMemorySize, SM1);
    cudaFuncSetAttribute(mma_gemm<256, 64, HID_DIM, OUT_DIM, true>,
                         cudaFuncAttributeMaxDynamicSharedMemorySize, SM2);

    const int NT1 = (N_DST1 + 63) / 64;    // 1719
    const int NT2 = (N_DST2 + 63) / 64;    // 157

    init_all<<<(N_SRC1 + T - 1) / T, T>>>(W1, W2);                             // 1
    count_all<<<(E1 + T - 1) / T, T>>>(src1, dst1, src2, dst2);                // 2
    scan_lb<<<NBT, 512>>>();                                                   // 3
    fill_csr<<<(E1 + T - 1) / T, T>>>(src1, dst1, src2, dst2);                 // 4
    gather1<<<(N_DST1 * 32 + T - 1) / T, T>>>(feat);                           // 5
    mma_gemm1<<<148, 256, SM1>>>(                                              // 6
        agg1h, agg1l, w1h, w1l, b1, attn1, h1, alpha1, N_DST1, NT1);
    gather2<<<(N_DST2 * 32 + T - 1) / T, T>>>();                               // 7
    mma_gemm<256, 64, HID_DIM, OUT_DIM, true><<<148, 256, SM2>>>(              // 8
        agg2, w2h, w2l, b2, attn2, out_h, out_alpha, N_DST2, NT2);
}

// round 14
// speedup vs baseline: 1.1022x; 1.0262x over previous
#include <cuda_runtime.h>
#include <cuda_bf16.h>
#include <math.h>
#include <stdint.h>

// ---------------- problem constants ----------------
#define N_SRC1 1210000
#define N_DST1 110000
#define N_SRC2 110000
#define N_DST2 10000
#define E1 1100000
#define E2 100000
#define IN_DIM 128
#define HID_DIM 256
#define OUT_DIM 128

// scan decomposition
#define SCAN_CHUNK 4096
#define NB1 ((N_DST1 + SCAN_CHUNK - 1) / SCAN_CHUNK)
#define NB2 ((N_DST2 + SCAN_CHUNK - 1) / SCAN_CHUNK)
#define NBT (NB1 + NB2)

// ---------------- scratch (device globals; no runtime alloc) ----------------
__device__ __nv_bfloat16 g_agg1h[(size_t)N_DST1 * IN_DIM];  // pre-split layer-1 agg
__device__ __nv_bfloat16 g_agg1l[(size_t)N_DST1 * IN_DIM];
__device__ float g_h1[(size_t)N_DST1 * HID_DIM];     // UNGATED layer-1 output
__device__ float g_alpha1[N_DST1];                   // layer-1 gate
__device__ float g_agg2[(size_t)N_DST2 * HID_DIM];
__device__ int   g_outdeg1[N_SRC1];
__device__ int   g_indeg1[N_DST1];
__device__ int   g_outdeg2[N_SRC2];
__device__ int   g_indeg2[N_DST2];
__device__ float g_invout1[N_SRC1];
__device__ float g_invin1[N_DST1];
__device__ float g_invout2[N_SRC2];
__device__ float g_invin2[N_DST2];
__device__ int g_offs1[N_DST1 + 1];
__device__ int g_cursor1[N_DST1];
__device__ int g_csr1[E1];
__device__ int g_offs2[N_DST2 + 1];
__device__ int g_cursor2[N_DST2];
__device__ int g_csr2[E2];
__device__ int g_bsum[NBT];
// split bf16 weights, transposed to [N][K]
__device__ __nv_bfloat16 g_w1h[HID_DIM * IN_DIM];
__device__ __nv_bfloat16 g_w1l[HID_DIM * IN_DIM];
__device__ __nv_bfloat16 g_w2h[OUT_DIM * HID_DIM];
__device__ __nv_bfloat16 g_w2l[OUT_DIM * HID_DIM];

// ---------------- helpers ----------------
__device__ __forceinline__ uint32_t smem_u32(const void* p) {
    uint32_t a;
    asm("{ .reg .u64 t; cvta.to.shared.u64 t, %1; cvt.u32.u64 %0, t; }"
        : "=r"(a) : "l"(p));
    return a;
}
__device__ __forceinline__ uint32_t packbf(__nv_bfloat16 a, __nv_bfloat16 b) {
    return ((uint32_t)__bfloat16_as_ushort(b) << 16) | __bfloat16_as_ushort(a);
}
__device__ __forceinline__ void split2(float a, float b, uint32_t& hi, uint32_t& lo) {
    __nv_bfloat16 ah = __float2bfloat16(a), bh = __float2bfloat16(b);
    __nv_bfloat16 al = __float2bfloat16(a - __bfloat162float(ah));
    __nv_bfloat16 bl = __float2bfloat16(b - __bfloat162float(bh));
    hi = packbf(ah, bh);
    lo = packbf(al, bl);
}
__device__ __forceinline__ void ldm4(uint32_t addr, uint32_t* r) {
    asm volatile("ldmatrix.sync.aligned.m8n8.x4.shared.b16 {%0,%1,%2,%3}, [%4];"
                 : "=r"(r[0]), "=r"(r[1]), "=r"(r[2]), "=r"(r[3]) : "r"(addr));
}
__device__ __forceinline__ void mma16816(float* d, const uint32_t* a,
                                         uint32_t b0, uint32_t b1) {
    asm volatile(
        "mma.sync.aligned.m16n8k16.row.col.f32.bf16.bf16.f32 "
        "{%0,%1,%2,%3}, {%4,%5,%6,%7}, {%8,%9}, {%0,%1,%2,%3};"
        : "+f"(d[0]), "+f"(d[1]), "+f"(d[2]), "+f"(d[3])
        : "r"(a[0]), "r"(a[1]), "r"(a[2]), "r"(a[3]), "r"(b0), "r"(b1));
}
__device__ __forceinline__ void cpa16(uint32_t dst, const void* src) {
    asm volatile("cp.async.cg.shared.global [%0], [%1], 16;" :: "r"(dst), "l"(src));
}
#define CP_COMMIT() asm volatile("cp.async.commit_group;" ::: "memory")
#define CP_WAIT0()  asm volatile("cp.async.wait_group 0;" ::: "memory")

// ---------------- 1. init: zero counters + split/transpose weights ----------------
__global__ void init_all(const float* __restrict__ W1, const float* __restrict__ W2) {
    int i = blockIdx.x * blockDim.x + threadIdx.x;
    if (i == 0) { g_offs1[N_DST1] = E1; g_offs2[N_DST2] = E2; }
    if (i < N_SRC1)  g_outdeg1[i] = 0;
    if (i < N_DST1) { g_indeg1[i] = 0; g_outdeg2[i] = 0; }
    if (i < N_DST2)  g_indeg2[i] = 0;
    if (i < IN_DIM * HID_DIM) {                  // W1 [128 k][256 n]
        int k = i / HID_DIM, n = i % HID_DIM;
        float x = W1[i];
        __nv_bfloat16 h = __float2bfloat16(x);
        __nv_bfloat16 l = __float2bfloat16(x - __bfloat162float(h));
        g_w1h[n * IN_DIM + k] = h;
        g_w1l[n * IN_DIM + k] = l;
    }
    int j = i - IN_DIM * HID_DIM;
    if (j >= 0 && j < HID_DIM * OUT_DIM) {       // W2 [256 k][128 n]
        int k = j / OUT_DIM, n = j % OUT_DIM;
        float x = W2[j];
        __nv_bfloat16 h = __float2bfloat16(x);
        __nv_bfloat16 l = __float2bfloat16(x - __bfloat162float(h));
        g_w2h[n * HID_DIM + k] = h;
        g_w2l[n * HID_DIM + k] = l;
    }
}

// ---------------- 2. degree counting (both layers) ----------------
__global__ void count_all(const int* __restrict__ s1, const int* __restrict__ d1,
                          const int* __restrict__ s2, const int* __restrict__ d2) {
    int i = blockIdx.x * blockDim.x + threadIdx.x;
    if (i < E1) { atomicAdd(&g_outdeg1[s1[i]], 1); atomicAdd(&g_indeg1[d1[i]], 1); }
    if (i < E2) { atomicAdd(&g_outdeg2[s2[i]], 1); atomicAdd(&g_indeg2[d2[i]], 1); }
}

// ---------------- 3. scan phase A: per-chunk reduce ----------------
__global__ void __launch_bounds__(512) scan_reduce() {
    int layer = (blockIdx.x < NB1) ? 0 : 1;
    const int* deg = layer ? g_indeg2 : g_indeg1;
    int n = layer ? N_DST2 : N_DST1;
    int chunk = layer ? (blockIdx.x - NB1) : blockIdx.x;
    int base = chunk * SCAN_CHUNK + threadIdx.x * 8;
    int s = 0;
#pragma unroll
    for (int l = 0; l < 8; l++) { int i = base + l; if (i < n) s += deg[i]; }
#pragma unroll
    for (int o = 16; o > 0; o >>= 1) s += __shfl_xor_sync(0xffffffffu, s, o);
    __shared__ int ws[16];
    int lane = threadIdx.x & 31, wid = threadIdx.x >> 5;
    if (lane == 0) ws[wid] = s;
    __syncthreads();
    if (threadIdx.x < 16) {
        int v = ws[threadIdx.x];
#pragma unroll
        for (int o = 8; o > 0; o >>= 1) v += __shfl_xor_sync(0xffffu, v, o);
        if (threadIdx.x == 0) g_bsum[blockIdx.x] = v;
    }
}

// ---------------- 4. scan phase B: apply (inline spine) ----------------
__global__ void __launch_bounds__(512) scan_apply() {
    int layer = (blockIdx.x < NB1) ? 0 : 1;
    const int* deg = layer ? g_indeg2 : g_indeg1;
    int* offs      = layer ? g_offs2 : g_offs1;
    int* cursor    = layer ? g_cursor2 : g_cursor1;
    int n          = layer ? N_DST2 : N_DST1;
    int lo         = layer ? NB1 : 0;
    int chunk = blockIdx.x - lo;
    int base = chunk * SCAN_CHUNK + threadIdx.x * 8;

    __shared__ int sPre;
    if (threadIdx.x < 32) {
        int v = ((int)threadIdx.x < chunk) ? g_bsum[lo + threadIdx.x] : 0;
#pragma unroll
        for (int o = 16; o > 0; o >>= 1) v += __shfl_xor_sync(0xffffffffu, v, o);
        if (threadIdx.x == 0) sPre = v;
    }

    int v[8], ex[8];
    int tsum = 0;
#pragma unroll
    for (int l = 0; l < 8; l++) {
        int i = base + l;
        v[l] = (i < n) ? deg[i] : 0;
        ex[l] = tsum;
        tsum += v[l];
    }
    int lane = threadIdx.x & 31, wid = threadIdx.x >> 5;
    int incl = tsum;
#pragma unroll
    for (int o = 1; o < 32; o <<= 1) {
        int y = __shfl_up_sync(0xffffffffu, incl, o);
        if (lane >= o) incl += y;
    }
    __shared__ int ws[16];
    if (lane == 31) ws[wid] = incl;
    __syncthreads();
    if (threadIdx.x < 16) {
        int w = ws[threadIdx.x];
#pragma unroll
        for (int o = 1; o < 16; o <<= 1) {
            int y = __shfl_up_sync(0xffffu, w, o);
            if ((int)threadIdx.x >= o) w += y;
        }
        ws[threadIdx.x] = w;
    }
    __syncthreads();
    int thread_excl = sPre + (wid ? ws[wid - 1] : 0) + (incl - tsum);
#pragma unroll
    for (int l = 0; l < 8; l++) {
        int i = base + l;
        if (i < n) { int e = thread_excl + ex[l]; offs[i] = e; cursor[i] = e; }
    }
}

// ---------------- 5. fill CSR + inverse-sqrt degrees (merged) ----------------
__global__ void fill_inv(const int* __restrict__ s1, const int* __restrict__ d1,
                         const int* __restrict__ s2, const int* __restrict__ d2) {
    int i = blockIdx.x * blockDim.x + threadIdx.x;
    if (i < E1) { int pos = atomicAdd(&g_cursor1[d1[i]], 1); g_csr1[pos] = s1[i]; }
    if (i < E2) { int pos = atomicAdd(&g_cursor2[d2[i]], 1); g_csr2[pos] = s2[i]; }
    if (i < N_SRC1) { int d = g_outdeg1[i]; g_invout1[i] = rsqrtf((float)(d < 1 ? 1 : d)); }
    if (i < N_DST1) {
        int d = g_indeg1[i];  g_invin1[i]  = rsqrtf((float)(d < 1 ? 1 : d));
        int e = g_outdeg2[i]; g_invout2[i] = rsqrtf((float)(e < 1 ? 1 : e));
    }
    if (i < N_DST2) { int d = g_indeg2[i]; g_invin2[i] = rsqrtf((float)(d < 1 ? 1 : d)); }
}

// ---------------- 6. layer-1 gather, edge-loop unrolled x4 for load MLP ---------
// FMAs applied in edge order (v0,v1,v2,v3 sequentially) -> bit-identical results.
__global__ void __launch_bounds__(256) gather1(const float* __restrict__ feat) {
    int warp = (blockIdx.x * blockDim.x + threadIdx.x) >> 5;
    int lane = threadIdx.x & 31;
    if (warp >= N_DST1) return;
    int beg = g_offs1[warp], end = g_offs1[warp + 1];
    float4 acc = make_float4(0.f, 0.f, 0.f, 0.f);
    for (int base = beg; base < end; base += 32) {
        int cnt = min(end - base, 32);
        int s_l = 0; float sc_l = 0.f;
        if (lane < cnt) { s_l = g_csr1[base + lane]; sc_l = g_invout1[s_l]; }
        int j = 0;
        for (; j + 4 <= cnt; j += 4) {
            int s0 = __shfl_sync(0xffffffffu, s_l, j);
            int s1 = __shfl_sync(0xffffffffu, s_l, j + 1);
            int s2 = __shfl_sync(0xffffffffu, s_l, j + 2);
            int s3 = __shfl_sync(0xffffffffu, s_l, j + 3);
            float c0 = __shfl_sync(0xffffffffu, sc_l, j);
            float c1 = __shfl_sync(0xffffffffu, sc_l, j + 1);
            float c2 = __shfl_sync(0xffffffffu, sc_l, j + 2);
            float c3 = __shfl_sync(0xffffffffu, sc_l, j + 3);
            float4 v0 = *(const float4*)(feat + (size_t)s0 * IN_DIM + lane * 4);
            float4 v1 = *(const float4*)(feat + (size_t)s1 * IN_DIM + lane * 4);
            float4 v2 = *(const float4*)(feat + (size_t)s2 * IN_DIM + lane * 4);
            float4 v3 = *(const float4*)(feat + (size_t)s3 * IN_DIM + lane * 4);
            acc.x = fmaf(v0.x, c0, acc.x); acc.y = fmaf(v0.y, c0, acc.y);
            acc.z = fmaf(v0.z, c0, acc.z); acc.w = fmaf(v0.w, c0, acc.w);
            acc.x = fmaf(v1.x, c1, acc.x); acc.y = fmaf(v1.y, c1, acc.y);
            acc.z = fmaf(v1.z, c1, acc.z); acc.w = fmaf(v1.w, c1, acc.w);
            acc.x = fmaf(v2.x, c2, acc.x); acc.y = fmaf(v2.y, c2, acc.y);
            acc.z = fmaf(v2.z, c2, acc.z); acc.w = fmaf(v2.w, c2, acc.w);
            acc.x = fmaf(v3.x, c3, acc.x); acc.y = fmaf(v3.y, c3, acc.y);
            acc.z = fmaf(v3.z, c3, acc.z); acc.w = fmaf(v3.w, c3, acc.w);
        }
        for (; j < cnt; j++) {
            int s = __shfl_sync(0xffffffffu, s_l, j);
            float sc = __shfl_sync(0xffffffffu, sc_l, j);
            float4 v = *(const float4*)(feat + (size_t)s * IN_DIM + lane * 4);
            acc.x = fmaf(v.x, sc, acc.x);
            acc.y = fmaf(v.y, sc, acc.y);
            acc.z = fmaf(v.z, sc, acc.z);
            acc.w = fmaf(v.w, sc, acc.w);
        }
    }
    float r = g_invin1[warp];
    uint32_t h0, l0, h1, l1;
    split2(acc.x * r, acc.y * r, h0, l0);
    split2(acc.z * r, acc.w * r, h1, l1);
    *(uint2*)(g_agg1h + (size_t)warp * IN_DIM + lane * 4) = make_uint2(h0, h1);
    *(uint2*)(g_agg1l + (size_t)warp * IN_DIM + lane * 4) = make_uint2(l0, l1);
}

// ---------------- 8. layer-2 gather (gate folded), edge-loop unrolled x2 --------
__global__ void __launch_bounds__(256) gather2() {
    int warp = (blockIdx.x * blockDim.x + threadIdx.x) >> 5;
    int lane = threadIdx.x & 31;
    if (warp >= N_DST2) return;
    int beg = g_offs2[warp], end = g_offs2[warp + 1];
    float4 a0 = make_float4(0.f, 0.f, 0.f, 0.f);
    float4 a1 = make_float4(0.f, 0.f, 0.f, 0.f);
    for (int base = beg; base < end; base += 32) {
        int cnt = min(end - base, 32);
        int s_l = 0; float sc_l = 0.f;
        if (lane < cnt) {
            s_l = g_csr2[base + lane];
            sc_l = g_invout2[s_l] * g_alpha1[s_l];
        }
        int j = 0;
        for (; j + 2 <= cnt; j += 2) {
            int s0 = __shfl_sync(0xffffffffu, s_l, j);
            int s1 = __shfl_sync(0xffffffffu, s_l, j + 1);
            float c0 = __shfl_sync(0xffffffffu, sc_l, j);
            float c1 = __shfl_sync(0xffffffffu, sc_l, j + 1);
            const float* r0 = g_h1 + (size_t)s0 * HID_DIM;
            const float* r1 = g_h1 + (size_t)s1 * HID_DIM;
            float4 u0 = *(const float4*)(r0 + lane * 4);
            float4 u1 = *(const float4*)(r0 + 128 + lane * 4);
            float4 w0 = *(const float4*)(r1 + lane * 4);
            float4 w1 = *(const float4*)(r1 + 128 + lane * 4);
            a0.x = fmaf(u0.x, c0, a0.x); a0.y = fmaf(u0.y, c0, a0.y);
            a0.z = fmaf(u0.z, c0, a0.z); a0.w = fmaf(u0.w, c0, a0.w);
            a1.x = fmaf(u1.x, c0, a1.x); a1.y = fmaf(u1.y, c0, a1.y);
            a1.z = fmaf(u1.z, c0, a1.z); a1.w = fmaf(u1.w, c0, a1.w);
            a0.x = fmaf(w0.x, c1, a0.x); a0.y = fmaf(w0.y, c1, a0.y);
            a0.z = fmaf(w0.z, c1, a0.z); a0.w = fmaf(w0.w, c1, a0.w);
            a1.x = fmaf(w1.x, c1, a1.x); a1.y = fmaf(w1.y, c1, a1.y);
            a1.z = fmaf(w1.z, c1, a1.z); a1.w = fmaf(w1.w, c1, a1.w);
        }
        for (; j < cnt; j++) {
            int s = __shfl_sync(0xffffffffu, s_l, j);
            float sc = __shfl_sync(0xffffffffu, sc_l, j);
            const float* row = g_h1 + (size_t)s * HID_DIM;
            float4 v0 = *(const float4*)(row + lane * 4);
            float4 v1 = *(const float4*)(row + 128 + lane * 4);
            a0.x = fmaf(v0.x, sc, a0.x); a0.y = fmaf(v0.y, sc, a0.y);
            a0.z = fmaf(v0.z, sc, a0.z); a0.w = fmaf(v0.w, sc, a0.w);
            a1.x = fmaf(v1.x, sc, a1.x); a1.y = fmaf(v1.y, sc, a1.y);
            a1.z = fmaf(v1.z, sc, a1.z); a1.w = fmaf(v1.w, sc, a1.w);
        }
    }
    float r = g_invin2[warp];
    float* orow = g_agg2 + (size_t)warp * HID_DIM;
    *(float4*)(orow + lane * 4) = make_float4(a0.x * r, a0.y * r, a0.z * r, a0.w * r);
    *(float4*)(orow + 128 + lane * 4) = make_float4(a1.x * r, a1.y * r, a1.z * r, a1.w * r);
}

// ---------------- 7. PIPELINED layer-1 GEMM (verified round-11 code) -----------
__global__ void __launch_bounds__(256, 1)
mma_gemm1(const __nv_bfloat16* __restrict__ aggh,
          const __nv_bfloat16* __restrict__ aggl,
          const __nv_bfloat16* __restrict__ wh, const __nv_bfloat16* __restrict__ wl,
          const float* __restrict__ bias, const float* __restrict__ attn,
          float* __restrict__ out, float* __restrict__ alpha_out,
          int nrows, int ntiles) {
    constexpr int M = 64, K = IN_DIM, N = HID_DIM;
    constexpr int NWN = 4, NWM = 2, MF = 2;
    constexpr int LDA = K + 8;
    constexpr int LDB = K + 8;
    constexpr int KS = K / 16;
    constexpr int AOFF = M * LDA * 2;      // bytes: hi block -> lo block
    constexpr int BUFB = 2 * AOFF;         // bytes per (hi+lo) buffer

    extern __shared__ char smem[];
    __nv_bfloat16* sA = (__nv_bfloat16*)smem;               // [2][2][M][LDA]
    __nv_bfloat16* sBh = sA + 2 * 2 * M * LDA;
    __nv_bfloat16* sBl = sBh + N * LDB;
    float* sBias  = (float*)(sBl + N * LDB);
    float* sAttn  = sBias + N;
    float* sRowP  = sAttn + N;             // [M][NWN]
    float* sAlpha = sRowP + M * NWN;       // [M]

    int tid = threadIdx.x, lane = tid & 31, wid = tid >> 5;
    int mw = wid & (NWM - 1), nw = wid / NWM;
    uint32_t sA32 = smem_u32(sA);
    uint32_t sBh32 = smem_u32(sBh), sBl32 = smem_u32(sBl);

    // prefetch tile 0 (buffer 0) via cp.async, then load W while it flies
    {
        int t0 = blockIdx.x;
#pragma unroll
        for (int l = 0; l < 4; l++) {
            int i = tid + l * 256;          // 0..1023
            int row = i >> 4, c = i & 15;
            int gr = t0 * M + row; if (gr >= nrows) gr = nrows - 1;
            cpa16(sA32 + row * (LDA * 2) + c * 16, aggh + (size_t)gr * K + c * 8);
            cpa16(sA32 + AOFF + row * (LDA * 2) + c * 16, aggl + (size_t)gr * K + c * 8);
        }
        CP_COMMIT();
    }
    for (int i = tid; i < N * K / 8; i += 256) {
        int n = i / (K / 8), k8 = (i % (K / 8)) * 8;
        *(uint4*)&sBh[n * LDB + k8] = *(const uint4*)&wh[n * K + k8];
        *(uint4*)&sBl[n * LDB + k8] = *(const uint4*)&wl[n * K + k8];
    }
    for (int c = tid; c < N; c += 256) { sBias[c] = bias[c]; sAttn[c] = attn[c]; }

    int quad = lane >> 3, r = lane & 7;
    int aRow = mw * (MF * 16) + (quad & 1) * 8 + r;
    int bRow = nw * 64 + (quad >> 1) * 8 + r;
    int aColB = (quad >> 1) * 16;
    int bColB = (quad & 1) * 16;

    int buf = 0;
    for (int t = blockIdx.x; t < ntiles; t += gridDim.x) {
        CP_WAIT0();
        __syncthreads();                    // buf holds tile t, W ready

        int tn = t + gridDim.x;
        if (tn < ntiles) {
            uint32_t base = sA32 + (buf ^ 1) * BUFB;
#pragma unroll
            for (int l = 0; l < 4; l++) {
                int i = tid + l * 256;
                int row = i >> 4, c = i & 15;
                int gr = tn * M + row; if (gr >= nrows) gr = nrows - 1;
                cpa16(base + row * (LDA * 2) + c * 16, aggh + (size_t)gr * K + c * 8);
                cpa16(base + AOFF + row * (LDA * 2) + c * 16, aggl + (size_t)gr * K + c * 8);
            }
        }
        CP_COMMIT();

        uint32_t sAh32 = sA32 + buf * BUFB;
        uint32_t sAl32 = sAh32 + AOFF;

        // ---- MMA mainloop (product-major) ----
        float c[MF][8][4];
#pragma unroll
        for (int mf = 0; mf < MF; mf++)
#pragma unroll
            for (int nf = 0; nf < 8; nf++)
#pragma unroll
                for (int q = 0; q < 4; q++) c[mf][nf][q] = 0.f;

#pragma unroll
        for (int ks = 0; ks < KS; ks++) {
            uint32_t ah[MF][4], al[MF][4];
#pragma unroll
            for (int mf = 0; mf < MF; mf++) {
                uint32_t off = (uint32_t)((aRow + mf * 16) * LDA) * 2 + ks * 32 + aColB;
                ldm4(sAh32 + off, ah[mf]);
                ldm4(sAl32 + off, al[mf]);
            }
#pragma unroll
            for (int np = 0; np < 4; np++) {
                uint32_t bh[4], bl[4];
                uint32_t off = (uint32_t)((bRow + np * 16) * LDB) * 2 + ks * 32 + bColB;
                ldm4(sBh32 + off, bh);
                ldm4(sBl32 + off, bl);
#pragma unroll
                for (int mf = 0; mf < MF; mf++) {
                    mma16816(c[mf][2 * np],     ah[mf], bh[0], bh[1]);
                    mma16816(c[mf][2 * np + 1], ah[mf], bh[2], bh[3]);
                }
#pragma unroll
                for (int mf = 0; mf < MF; mf++) {
                    mma16816(c[mf][2 * np],     ah[mf], bl[0], bl[1]);
                    mma16816(c[mf][2 * np + 1], ah[mf], bl[2], bl[3]);
                }
#pragma unroll
                for (int mf = 0; mf < MF; mf++) {
                    mma16816(c[mf][2 * np],     al[mf], bh[0], bh[1]);
                    mma16816(c[mf][2 * np + 1], al[mf], bh[2], bh[3]);
                }
            }
        }

        // ---- epilogue ----
        int colq = (lane & 3) * 2;
        int rq = lane >> 2;
        float p[MF][2];
#pragma unroll
        for (int mf = 0; mf < MF; mf++) { p[mf][0] = 0.f; p[mf][1] = 0.f; }
#pragma unroll
        for (int mf = 0; mf < MF; mf++)
#pragma unroll
            for (int nf = 0; nf < 8; nf++) {
                int col = nw * 64 + nf * 8 + colq;
                float b0 = sBias[col], b1 = sBias[col + 1];
                float w0 = sAttn[col], w1 = sAttn[col + 1];
                c[mf][nf][0] += b0; c[mf][nf][1] += b1;
                c[mf][nf][2] += b0; c[mf][nf][3] += b1;
                p[mf][0] = fmaf(c[mf][nf][0], w0, fmaf(c[mf][nf][1], w1, p[mf][0]));
                p[mf][1] = fmaf(c[mf][nf][2], w0, fmaf(c[mf][nf][3], w1, p[mf][1]));
            }
#pragma unroll
        for (int mf = 0; mf < MF; mf++) {
#pragma unroll
            for (int o = 1; o <= 2; o <<= 1) {
                p[mf][0] += __shfl_xor_sync(0xffffffffu, p[mf][0], o);
                p[mf][1] += __shfl_xor_sync(0xffffffffu, p[mf][1], o);
            }
            if ((lane & 3) == 0) {
                int row0 = mw * (MF * 16) + mf * 16 + rq;
                sRowP[row0 * NWN + nw]       = p[mf][0];
                sRowP[(row0 + 8) * NWN + nw] = p[mf][1];
            }
        }
        __syncthreads();
        if (tid < M) {
            float s = 0.f;
#pragma unroll
            for (int j = 0; j < NWN; j++) s += sRowP[tid * NWN + j];
            float a = 1.f / (1.f + __expf(-s));
            int g2 = t * M + tid;
            if (g2 < nrows) alpha_out[g2] = a;
        }

        // ---- store (ungated) ----
#pragma unroll
        for (int mf = 0; mf < MF; mf++)
#pragma unroll
            for (int nf = 0; nf < 8; nf++) {
                int row0 = mw * (MF * 16) + mf * 16 + rq;
                int col = nw * 64 + nf * 8 + colq;
#pragma unroll
                for (int h = 0; h < 2; h++) {
                    int row = row0 + h * 8;
                    int gr = t * M + row;
                    if (gr < nrows)
                        *(float2*)(out + (size_t)gr * N + col) =
                            make_float2(c[mf][nf][2 * h], c[mf][nf][2 * h + 1]);
                }
            }
        buf ^= 1;
    }
}

// ---------------- 9. layer-2 GEMM (verified template, 256 thr) ----------------
template <int THREADS, int M, int K, int N, bool GATED>
__global__ void __launch_bounds__(THREADS, 1)
mma_gemm(const float* __restrict__ agg,
         const __nv_bfloat16* __restrict__ wh, const __nv_bfloat16* __restrict__ wl,
         const float* __restrict__ bias, const float* __restrict__ attn,
         float* __restrict__ out, float* __restrict__ alpha_out,
         int nrows, int ntiles) {
    constexpr int NW  = THREADS / 32;
    constexpr int NWN = N / 64;
    constexpr int NWM = NW / NWN;
    constexpr int MF  = M / (NWM * 16);
    constexpr int LDA = K + 8;
    constexpr int LDB = K + 8;
    constexpr int KS  = K / 16;
    constexpr int TPR = THREADS / M;

    extern __shared__ char smem[];
    __nv_bfloat16* sAh = (__nv_bfloat16*)smem;
    __nv_bfloat16* sAl = sAh + M * LDA;
    __nv_bfloat16* sBh = sAl + M * LDA;
    __nv_bfloat16* sBl = sBh + N * LDB;
    float* sBias  = (float*)(sBl + N * LDB);
    float* sAttn  = sBias + N;
    float* sRowP  = sAttn + N;
    float* sAlpha = sRowP + M * NWN;

    int tid = threadIdx.x, lane = tid & 31, wid = tid >> 5;
    int mw = wid & (NWM - 1), nw = wid / NWM;

    for (int i = tid; i < N * K / 8; i += THREADS) {
        int n = i / (K / 8), k8 = (i % (K / 8)) * 8;
        *(uint4*)&sBh[n * LDB + k8] = *(const uint4*)&wh[n * K + k8];
        *(uint4*)&sBl[n * LDB + k8] = *(const uint4*)&wl[n * K + k8];
    }
    for (int c = tid; c < N; c += THREADS) { sBias[c] = bias[c]; sAttn[c] = attn[c]; }

    uint32_t sAh32 = smem_u32(sAh), sAl32 = smem_u32(sAl);
    uint32_t sBh32 = smem_u32(sBh), sBl32 = smem_u32(sBl);

    int quad = lane >> 3, r = lane & 7;
    int aRow = mw * (MF * 16) + (quad & 1) * 8 + r;
    int bRow = nw * 64 + (quad >> 1) * 8 + r;
    int aColB = (quad >> 1) * 16;
    int bColB = (quad & 1) * 16;

    for (int t = blockIdx.x; t < ntiles; t += gridDim.x) {
        {
            int row = tid / TPR, cg = tid % TPR;
            int gr = t * M + row;
            bool v = gr < nrows;
            const float4* ap = (const float4*)(agg + (size_t)gr * K + cg * (K / TPR));
#pragma unroll
            for (int q = 0; q < K / (4 * TPR); q++) {
                float4 f = v ? ap[q] : make_float4(0.f, 0.f, 0.f, 0.f);
                uint32_t h0, l0, h1, l1;
                split2(f.x, f.y, h0, l0);
                split2(f.z, f.w, h1, l1);
                int col = cg * (K / TPR) + q * 4;
                *(uint32_t*)&sAh[row * LDA + col]     = h0;
                *(uint32_t*)&sAh[row * LDA + col + 2] = h1;
                *(uint32_t*)&sAl[row * LDA + col]     = l0;
                *(uint32_t*)&sAl[row * LDA + col + 2] = l1;
            }
        }
        __syncthreads();

        float c[MF][8][4];
#pragma unroll
        for (int mf = 0; mf < MF; mf++)
#pragma unroll
            for (int nf = 0; nf < 8; nf++)
#pragma unroll
                for (int q = 0; q < 4; q++) c[mf][nf][q] = 0.f;

#pragma unroll
        for (int ks = 0; ks < KS; ks++) {
            uint32_t ah[MF][4], al[MF][4];
#pragma unroll
            for (int mf = 0; mf < MF; mf++) {
                uint32_t off = (uint32_t)((aRow + mf * 16) * LDA) * 2 + ks * 32 + aColB;
                ldm4(sAh32 + off, ah[mf]);
                ldm4(sAl32 + off, al[mf]);
            }
#pragma unroll
            for (int np = 0; np < 4; np++) {
                uint32_t bh[4], bl[4];
                uint32_t off = (uint32_t)((bRow + np * 16) * LDB) * 2 + ks * 32 + bColB;
                ldm4(sBh32 + off, bh);
                ldm4(sBl32 + off, bl);
#pragma unroll
                for (int mf = 0; mf < MF; mf++) {
                    mma16816(c[mf][2 * np],     ah[mf], bh[0], bh[1]);
                    mma16816(c[mf][2 * np + 1], ah[mf], bh[2], bh[3]);
                }
#pragma unroll
                for (int mf = 0; mf < MF; mf++) {
                    mma16816(c[mf][2 * np],     ah[mf], bl[0], bl[1]);
                    mma16816(c[mf][2 * np + 1], ah[mf], bl[2], bl[3]);
                }
#pragma unroll
                for (int mf = 0; mf < MF; mf++) {
                    mma16816(c[mf][2 * np],     al[mf], bh[0], bh[1]);
                    mma16816(c[mf][2 * np + 1], al[mf], bh[2], bh[3]);
                }
            }
        }

        int colq = (lane & 3) * 2;
        int rq = lane >> 2;
        float p[MF][2];
#pragma unroll
        for (int mf = 0; mf < MF; mf++) { p[mf][0] = 0.f; p[mf][1] = 0.f; }
#pragma unroll
        for (int mf = 0; mf < MF; mf++)
#pragma unroll
            for (int nf = 0; nf < 8; nf++) {
                int col = nw * 64 + nf * 8 + colq;
                float b0 = sBias[col], b1 = sBias[col + 1];
                float w0 = sAttn[col], w1 = sAttn[col + 1];
                c[mf][nf][0] += b0; c[mf][nf][1] += b1;
                c[mf][nf][2] += b0; c[mf][nf][3] += b1;
                p[mf][0] = fmaf(c[mf][nf][0], w0, fmaf(c[mf][nf][1], w1, p[mf][0]));
                p[mf][1] = fmaf(c[mf][nf][2], w0, fmaf(c[mf][nf][3], w1, p[mf][1]));
            }
#pragma unroll
        for (int mf = 0; mf < MF; mf++) {
#pragma unroll
            for (int o = 1; o <= 2; o <<= 1) {
                p[mf][0] += __shfl_xor_sync(0xffffffffu, p[mf][0], o);
                p[mf][1] += __shfl_xor_sync(0xffffffffu, p[mf][1], o);
            }
            if ((lane & 3) == 0) {
                int row0 = mw * (MF * 16) + mf * 16 + rq;
                sRowP[row0 * NWN + nw]       = p[mf][0];
                sRowP[(row0 + 8) * NWN + nw] = p[mf][1];
            }
        }
        __syncthreads();
        if (tid < M) {
            float s = 0.f;
#pragma unroll
            for (int j = 0; j < NWN; j++) s += sRowP[tid * NWN + j];
            float a = 1.f / (1.f + __expf(-s));
            sAlpha[tid] = a;
            int g2 = t * M + tid;
            if (g2 < nrows) alpha_out[g2] = a;
        }
        __syncthreads();

#pragma unroll
        for (int mf = 0; mf < MF; mf++)
#pragma unroll
            for (int nf = 0; nf < 8; nf++) {
                int row0 = mw * (MF * 16) + mf * 16 + rq;
                int col = nw * 64 + nf * 8 + colq;
#pragma unroll
                for (int h = 0; h < 2; h++) {
                    int row = row0 + h * 8;
                    int gr = t * M + row;
                    if (gr < nrows) {
                        float a = GATED ? sAlpha[row] : 1.f;
                        *(float2*)(out + (size_t)gr * N + col) =
                            make_float2(c[mf][nf][2 * h] * a, c[mf][nf][2 * h + 1] * a);
                    }
                }
            }
    }
}

// ---------------- host launch ----------------
static inline void* symaddr(const void* sym) {
    void* p = nullptr;
    cudaGetSymbolAddress(&p, sym);
    return p;
}

extern "C" void kernel_launch(void* const* d_in, const int* in_sizes, int n_in,
                              void* d_out, int out_size) {
    const float* feat  = (const float*)d_in[0];
    const float* W1    = (const float*)d_in[1];
    const float* b1    = (const float*)d_in[2];
    const float* attn1 = (const float*)d_in[3];
    const float* W2    = (const float*)d_in[4];
    const float* b2    = (const float*)d_in[5];
    const float* attn2 = (const float*)d_in[6];
    const int* src1 = (const int*)d_in[7];
    const int* dst1 = (const int*)d_in[8];
    const int* src2 = (const int*)d_in[9];
    const int* dst2 = (const int*)d_in[10];

    float* out_h     = (float*)d_out;                             // (10000, 128)
    float* out_alpha = (float*)d_out + (size_t)N_DST2 * OUT_DIM;  // (10000, 1)

    __nv_bfloat16* agg1h = (__nv_bfloat16*)symaddr(g_agg1h);
    __nv_bfloat16* agg1l = (__nv_bfloat16*)symaddr(g_agg1l);
    float* h1     = (float*)symaddr(g_h1);
    float* alpha1 = (float*)symaddr(g_alpha1);
    float* agg2   = (float*)symaddr(g_agg2);
    __nv_bfloat16* w1h = (__nv_bfloat16*)symaddr(g_w1h);
    __nv_bfloat16* w1l = (__nv_bfloat16*)symaddr(g_w1l);
    __nv_bfloat16* w2h = (__nv_bfloat16*)symaddr(g_w2h);
    __nv_bfloat16* w2l = (__nv_bfloat16*)symaddr(g_w2l);

    const int T = 256;

    // dynamic smem sizes
    const int LDA1 = IN_DIM + 8;
    const int SM1 = (2 * 2 * 64 * LDA1 + 2 * HID_DIM * LDA1) * 2
                  + (2 * HID_DIM + 64 * 4 + 64) * 4;               // ~207 KB
    const int LDA2 = HID_DIM + 8;
    const int SM2 = (2 * 64 * LDA2 + 2 * OUT_DIM * LDA2) * 2
                  + (2 * OUT_DIM + 64 * 2 + 64) * 4;               // ~204 KB

    cudaFuncSetAttribute(mma_gemm1,
                         cudaFuncAttributeMaxDynamicSharedMemorySize, SM1);
    cudaFuncSetAttribute(mma_gemm<256, 64, HID_DIM, OUT_DIM, true>,
                         cudaFuncAttributeMaxDynamicSharedMemorySize, SM2);

    const int NT1 = (N_DST1 + 63) / 64;    // 1719
    const int NT2 = (N_DST2 + 63) / 64;    // 157

    init_all<<<(N_SRC1 + T - 1) / T, T>>>(W1, W2);                             // 1
    count_all<<<(E1 + T - 1) / T, T>>>(src1, dst1, src2, dst2);                // 2
    scan_reduce<<<NBT, 512>>>();                                               // 3
    scan_apply<<<NBT, 512>>>();                                                // 4
    fill_inv<<<(N_SRC1 + T - 1) / T, T>>>(src1, dst1, src2, dst2);             // 5
    gather1<<<(N_DST1 * 32 + T - 1) / T, T>>>(feat);                           // 6
    mma_gemm1<<<148, 256, SM1>>>(                                              // 7
        agg1h, agg1l, w1h, w1l, b1, attn1, h1, alpha1, N_DST1, NT1);
    gather2<<<(N_DST2 * 32 + T - 1) / T, T>>>();                               // 8
    mma_gemm<256, 64, HID_DIM, OUT_DIM, true><<<148, 256, SM2>>>(              // 9
        agg2, w2h, w2l, b2, attn2, out_h, out_alpha, N_DST2, NT2);
}